// round 12
// baseline (speedup 1.0000x reference)
#include <cuda_runtime.h>
#include <cuda_fp16.h>
#include <cstdint>

#define NN 100000
#define EE 1600000
#define ETOT (EE + NN)
#define BB 64

// ---------------- device scratch (static: no allocs allowed) ----------------
__device__ int    g_deg[NN];          // zero-initialized; k_pool re-zeroes each replay
__device__ int    g_off[NN + 1];
__device__ int    g_cursor[NN];
__device__ int    g_csr[ETOT];
__device__ __half g_h16[NN * 64];     // fp16 gather payload (softmax weights stay fp32)
__device__ float  g_as[NN * 4];
__device__ float  g_ad[NN * 4];
__device__ float  g_x1[NN * 64];
__device__ float  g_x2[NN * 16];
__device__ float  g_x3[NN * 16];
__device__ float  g_pool[BB * 16];    // zero-initialized; k_mlp re-zeroes after read
__device__ float  g_cnt[BB];

// per-block int64-vs-int32 probe of the EDGE array (values random in [0,1e5):
// odd 32-bit words all zero <=> little-endian int64 high words)
__device__ __forceinline__ int probe_is64(const void* ep, int* smem_flag) {
    if (threadIdx.x == 0) {
        const int* e32 = (const int*)ep;
        int z = 0;
#pragma unroll
        for (int j = 0; j < 64; j++) z |= e32[2 * j + 1];
        *smem_flag = (z == 0) ? 1 : 0;
    }
    __syncthreads();
    return *smem_flag;
}

// load 4 contiguous halves as float4 with a single LDG.64
__device__ __forceinline__ float4 ldh4(const __half* p) {
    uint2 r = *(const uint2*)p;
    __half2 h0 = *reinterpret_cast<__half2*>(&r.x);
    __half2 h1 = *reinterpret_cast<__half2*>(&r.y);
    float2 f0 = __half22float2(h0), f1 = __half22float2(h1);
    return make_float4(f0.x, f0.y, f1.x, f1.y);
}

// ---------------- build: histogram destination degrees (+ self loops) ----------------
__global__ void k_build(const void* ep) {
    __shared__ int is64_s;
    int is64 = probe_is64(ep, &is64_s);
    int i = blockIdx.x * blockDim.x + threadIdx.x;
    if (i >= ETOT) return;
    int d;
    if (i < EE) {
        d = is64 ? (int)((const long long*)ep)[EE + i] : ((const int*)ep)[EE + i];
    } else {
        d = i - EE;    // self loop
    }
    atomicAdd(&g_deg[d], 1);
}

// ---------------- single-kernel exclusive scan (block-redundant prefix) ----------------
// Block b: (1) all 1024 threads reduce-sum g_deg[0 .. b*1024) (L2-resident),
// (2) block-scan its own 1024 degrees. Replaces the old scan1+scan3 pair.
__global__ void k_scan() {
    __shared__ int warp_sums[32];
    __shared__ int carry_s;
    int bid = blockIdx.x, tid = threadIdx.x;
    int lane = tid & 31, wid = tid >> 5;
    int pre = bid * 1024;

    // ---- carry = sum of all degrees below this block ----
    int c = 0;
    for (int j = tid; j < pre; j += 1024) c += g_deg[j];
#pragma unroll
    for (int o = 16; o >= 1; o >>= 1) c += __shfl_xor_sync(0xffffffffu, c, o);
    if (lane == 0) warp_sums[wid] = c;
    __syncthreads();
    if (wid == 0) {
        int s = warp_sums[lane];
#pragma unroll
        for (int o = 16; o >= 1; o >>= 1) s += __shfl_xor_sync(0xffffffffu, s, o);
        if (lane == 0) carry_s = s;
    }
    __syncthreads();
    int carry = carry_s;
    __syncthreads();   // warp_sums about to be reused

    // ---- exclusive scan of own 1024 degrees ----
    int i = pre + tid;
    int v = (i < NN) ? g_deg[i] : 0;
    int x = v;
#pragma unroll
    for (int o = 1; o < 32; o <<= 1) {
        int y = __shfl_up_sync(0xffffffffu, x, o);
        if (lane >= o) x += y;
    }
    if (lane == 31) warp_sums[wid] = x;
    __syncthreads();
    if (wid == 0) {
        int s = warp_sums[lane];
#pragma unroll
        for (int o = 1; o < 32; o <<= 1) {
            int y = __shfl_up_sync(0xffffffffu, s, o);
            if (lane >= o) s += y;
        }
        warp_sums[lane] = s;
    }
    __syncthreads();
    int excl = x - v + (wid > 0 ? warp_sums[wid - 1] : 0) + carry;
    if (i < NN) {
        g_off[i] = excl;
        g_cursor[i] = excl;
    }
    if (bid == 0 && tid == 0) g_off[NN] = ETOT;   // total is a compile-time constant
}

// ---------------- scatter: read edges directly, place src into CSR by dst ----------------
__global__ void k_scatter(const void* ep) {
    __shared__ int is64_s;
    int is64 = probe_is64(ep, &is64_s);
    int i = blockIdx.x * blockDim.x + threadIdx.x;
    if (i >= ETOT) return;
    int s, d;
    if (i < EE) {
        if (is64) {
            const long long* e = (const long long*)ep;
            s = (int)e[i]; d = (int)e[EE + i];
        } else {
            const int* e = (const int*)ep;
            s = e[i]; d = e[EE + i];
        }
    } else {
        s = d = i - EE;    // self loop
    }
    int p = atomicAdd(&g_cursor[d], 1);
    g_csr[p] = s;
}

// ---------------- transform: 4 channels/thread, 4 nodes/thread, k-outer ----------------
// Per k-step: one LDS.128 of W (shared by 4 nodes) + 4 broadcast scalar LDS of x
// + 16 FFMA. Live state ~35 regs -> no spills.
template <int FIN>
__global__ void k_transform(const float* __restrict__ x, const float* __restrict__ W,
                            const float* __restrict__ a_s, const float* __restrict__ a_d,
                            __half* __restrict__ hout, float* __restrict__ aso,
                            float* __restrict__ ado) {
    constexpr int NODES = 64;
    __shared__ float Ws[FIN * 64];          // [k][64]
    __shared__ float xs[NODES * FIN];       // [node][FIN]
    int tid = threadIdx.x;
    for (int k = tid; k < FIN * 64; k += 256) Ws[k] = W[k];
    long long xbase = (long long)blockIdx.x * NODES * FIN;
    for (int m = tid; m < NODES * FIN; m += 256) {
        long long gi = xbase + m;
        xs[m] = (gi < (long long)NN * FIN) ? x[gi] : 0.f;
    }
    __syncthreads();

    int tj = tid & 15;          // channel group: channels tj*4 .. tj*4+3
    int tn = tid >> 4;          // node slot: nodes g*16+tn
    int j4 = tj * 4;

    float4 acc[4];
#pragma unroll
    for (int g = 0; g < 4; g++) acc[g] = make_float4(0.f, 0.f, 0.f, 0.f);

#pragma unroll 4
    for (int k = 0; k < FIN; k++) {
        float4 wv = *(const float4*)&Ws[k * 64 + j4];
#pragma unroll
        for (int g = 0; g < 4; g++) {
            float xv = xs[(g * 16 + tn) * FIN + k];
            acc[g].x += xv * wv.x;
            acc[g].y += xv * wv.y;
            acc[g].z += xv * wv.z;
            acc[g].w += xv * wv.w;
        }
    }

    // attention partials: this thread's 4 channels all lie in head = tj>>2
    float4 asv = __ldg((const float4*)(a_s + j4));
    float4 adv = __ldg((const float4*)(a_d + j4));
    int nblock = blockIdx.x * NODES;
#pragma unroll
    for (int g = 0; g < 4; g++) {
        int n = nblock + g * 16 + tn;
        float ps = acc[g].x * asv.x + acc[g].y * asv.y + acc[g].z * asv.z + acc[g].w * asv.w;
        float pd = acc[g].x * adv.x + acc[g].y * adv.y + acc[g].z * adv.z + acc[g].w * adv.w;
        ps += __shfl_xor_sync(0xffffffffu, ps, 1);
        ps += __shfl_xor_sync(0xffffffffu, ps, 2);
        pd += __shfl_xor_sync(0xffffffffu, pd, 1);
        pd += __shfl_xor_sync(0xffffffffu, pd, 2);
        if ((tj & 3) == 0 && n < NN) {
            int head = tj >> 2;
            aso[n * 4 + head] = ps;
            ado[n * 4 + head] = pd;
        }
        if (n < NN) {
            __half2 lo = __floats2half2_rn(acc[g].x, acc[g].y);
            __half2 hi = __floats2half2_rn(acc[g].z, acc[g].w);
            uint2 pk;
            pk.x = *reinterpret_cast<unsigned int*>(&lo);
            pk.y = *reinterpret_cast<unsigned int*>(&hi);
            *(uint2*)(hout + n * 64 + j4) = pk;
        }
    }
}

// ---------------- warp-per-destination softmax aggregation (fp16 payload) ----------------
// MODE 0: concat (64) + bias + ELU ; 1: head-mean + bias + ELU ; 2: head-mean + bias.
template <int MODE>
__global__ void k_agg(const __half* __restrict__ h, const float* __restrict__ as_,
                      const float* __restrict__ ad_, const float* __restrict__ bias,
                      float* __restrict__ out) {
    int w = (blockIdx.x * blockDim.x + threadIdx.x) >> 5;
    if (w >= NN) return;
    int lane = threadIdx.x & 31;
    int half_ = lane >> 4;         // which edge of the pair
    int q = lane & 15;             // channel group: channels q*4..q*4+3
    int head = q >> 2;
    float adh = __ldg(&ad_[w * 4 + head]);
    float den = 0.f;
    float4 acc = make_float4(0.f, 0.f, 0.f, 0.f);
    int s0 = __ldg(&g_off[w]), s1 = __ldg(&g_off[w + 1]);
    int last = s1 - 1;             // degree >= 1 (self loop)
    for (int i = s0; i < s1; i += 4) {
        int ia = i + half_;
        int ib = i + 2 + half_;
        bool va = ia < s1, vb = ib < s1;
        int sa = __ldg(&g_csr[min(ia, last)]);
        int sb = __ldg(&g_csr[min(ib, last)]);
        float ea = __ldg(&as_[sa * 4 + head]);
        float eb = __ldg(&as_[sb * 4 + head]);
        float4 ha = ldh4(h + sa * 64 + q * 4);
        float4 hb = ldh4(h + sb * 64 + q * 4);
        ea += adh; ea = ea > 0.f ? ea : 0.2f * ea;
        eb += adh; eb = eb > 0.f ? eb : 0.2f * eb;
        float wa = va ? __expf(ea) : 0.f;
        float wb = vb ? __expf(eb) : 0.f;
        den += wa + wb;
        acc.x += wa * ha.x + wb * hb.x;
        acc.y += wa * ha.y + wb * hb.y;
        acc.z += wa * ha.z + wb * hb.z;
        acc.w += wa * ha.w + wb * hb.w;
    }
    den   += __shfl_xor_sync(0xffffffffu, den,   16);
    acc.x += __shfl_xor_sync(0xffffffffu, acc.x, 16);
    acc.y += __shfl_xor_sync(0xffffffffu, acc.y, 16);
    acc.z += __shfl_xor_sync(0xffffffffu, acc.z, 16);
    acc.w += __shfl_xor_sync(0xffffffffu, acc.w, 16);
    float inv = 1.f / den;
    float4 o4;
    o4.x = acc.x * inv; o4.y = acc.y * inv; o4.z = acc.z * inv; o4.w = acc.w * inv;
    if (MODE == 0) {
        if (half_ == 0) {
            float4 b4 = __ldg((const float4*)(bias + q * 4));
            o4.x += b4.x; o4.y += b4.y; o4.z += b4.z; o4.w += b4.w;
            o4.x = o4.x > 0.f ? o4.x : expm1f(o4.x);
            o4.y = o4.y > 0.f ? o4.y : expm1f(o4.y);
            o4.z = o4.z > 0.f ? o4.z : expm1f(o4.z);
            o4.w = o4.w > 0.f ? o4.w : expm1f(o4.w);
            *(float4*)(out + w * 64 + q * 4) = o4;
        }
    } else {
#pragma unroll
        for (int o = 4; o <= 8; o <<= 1) {
            o4.x += __shfl_xor_sync(0xffffffffu, o4.x, o);
            o4.y += __shfl_xor_sync(0xffffffffu, o4.y, o);
            o4.z += __shfl_xor_sync(0xffffffffu, o4.z, o);
            o4.w += __shfl_xor_sync(0xffffffffu, o4.w, o);
        }
        if (half_ == 0 && q < 4) {
            float4 b4 = __ldg((const float4*)(bias + q * 4));
            float4 v;
            v.x = 0.25f * o4.x + b4.x;
            v.y = 0.25f * o4.y + b4.y;
            v.z = 0.25f * o4.z + b4.z;
            v.w = 0.25f * o4.w + b4.w;
            if (MODE == 1) {
                v.x = v.x > 0.f ? v.x : expm1f(v.x);
                v.y = v.y > 0.f ? v.y : expm1f(v.y);
                v.z = v.z > 0.f ? v.z : expm1f(v.z);
                v.w = v.w > 0.f ? v.w : expm1f(v.w);
            }
            *(float4*)(out + w * 16 + q * 4) = v;
        }
    }
}

// --------- mean pooling (sorted batch -> run-length) + re-zero g_deg slice ---------
__global__ void k_pool(const void* bp, const void* ep) {
    __shared__ int is64_s;
    int is64 = probe_is64(ep, &is64_s);      // probe EDGES (batch's words can be 0)
    constexpr int NPB = 1024;                // nodes per block
    // reset this block's degree-histogram slice for the next replay
    for (int j = threadIdx.x; j < NPB; j += blockDim.x) {
        int n = blockIdx.x * NPB + j;
        if (n < NN) g_deg[n] = 0;
    }
    int c = threadIdx.x & 15;
    int nrel = threadIdx.x >> 4;             // 0..15
    int base = blockIdx.x * NPB;
    float acc = 0.f, cnt = 0.f;
    int bcur = -1;
    for (int k = 0; k < NPB / 16; k++) {
        int n = base + k * 16 + nrel;
        if (n >= NN) break;
        int b = is64 ? (int)((const long long*)bp)[n] : ((const int*)bp)[n];
        if (b != bcur) {
            if (bcur >= 0) {
                atomicAdd(&g_pool[bcur * 16 + c], acc);
                if (c == 0) atomicAdd(&g_cnt[bcur], cnt);
            }
            bcur = b; acc = 0.f; cnt = 0.f;
        }
        acc += g_x3[n * 16 + c];
        cnt += 1.f;
    }
    if (bcur >= 0) {
        atomicAdd(&g_pool[bcur * 16 + c], acc);
        if (c == 0) atomicAdd(&g_cnt[bcur], cnt);
    }
}

// ---------------- tiny MLP head (single block) — also resets pool state ----------------
__global__ void k_mlp(const float* __restrict__ stats,
                      const float* __restrict__ fw1, const float* __restrict__ fb1,
                      const float* __restrict__ fw2, const float* __restrict__ fb2,
                      const float* __restrict__ fw3, const float* __restrict__ fb3,
                      float* __restrict__ out) {
    __shared__ float zin[BB * 32];
    __shared__ float z1[BB * 32];
    __shared__ float z2[BB * 16];
    int tid = threadIdx.x;
    for (int t = tid; t < BB * 32; t += blockDim.x) {
        int b = t >> 5, k = t & 31;
        zin[t] = (k < 16) ? g_pool[b * 16 + k] / fmaxf(g_cnt[b], 1.f)
                          : stats[b * 16 + (k - 16)];
    }
    __syncthreads();
    // reset pool accumulators for the next graph replay (deterministic invariant)
    if (tid < BB * 16) g_pool[tid] = 0.f;
    if (tid < BB) g_cnt[tid] = 0.f;
    for (int t = tid; t < BB * 32; t += blockDim.x) {
        int b = t >> 5, j = t & 31;
        float a = fb1[j];
#pragma unroll
        for (int k = 0; k < 32; k++) a += zin[b * 32 + k] * fw1[k * 32 + j];
        z1[t] = fmaxf(a, 0.f);
    }
    __syncthreads();
    for (int t = tid; t < BB * 16; t += blockDim.x) {
        int b = t >> 4, j = t & 15;
        float a = fb2[j];
#pragma unroll
        for (int k = 0; k < 32; k++) a += z1[b * 32 + k] * fw2[k * 16 + j];
        z2[t] = fmaxf(a, 0.f);
    }
    __syncthreads();
    for (int t = tid; t < BB; t += blockDim.x) {
        float a = fb3[0];
#pragma unroll
        for (int k = 0; k < 16; k++) a += z2[t * 16 + k] * fw3[k];
        out[t] = a;
    }
}

// ---------------- launcher ----------------
extern "C" void kernel_launch(void* const* d_in, const int* in_sizes, int n_in,
                              void* d_out, int out_size) {
    const float* x     = (const float*)d_in[0];
    const float* stats = (const float*)d_in[1];
    const float* W1  = (const float*)d_in[2];
    const float* a1s = (const float*)d_in[3];
    const float* a1d = (const float*)d_in[4];
    const float* b1  = (const float*)d_in[5];
    const float* W2  = (const float*)d_in[6];
    const float* a2s = (const float*)d_in[7];
    const float* a2d = (const float*)d_in[8];
    const float* b2  = (const float*)d_in[9];
    const float* W3  = (const float*)d_in[10];
    const float* a3s = (const float*)d_in[11];
    const float* a3d = (const float*)d_in[12];
    const float* b3  = (const float*)d_in[13];
    const float* fw1 = (const float*)d_in[14];
    const float* fb1 = (const float*)d_in[15];
    const float* fw2 = (const float*)d_in[16];
    const float* fb2 = (const float*)d_in[17];
    const float* fw3 = (const float*)d_in[18];
    const float* fb3 = (const float*)d_in[19];
    const void*  edges = d_in[20];
    const void*  batch = d_in[21];
    float* out = (float*)d_out;

    __half* dg_h; cudaGetSymbolAddress((void**)&dg_h,  g_h16);
    float* dg_as; cudaGetSymbolAddress((void**)&dg_as, g_as);
    float* dg_ad; cudaGetSymbolAddress((void**)&dg_ad, g_ad);
    float* dg_x1; cudaGetSymbolAddress((void**)&dg_x1, g_x1);
    float* dg_x2; cudaGetSymbolAddress((void**)&dg_x2, g_x2);
    float* dg_x3; cudaGetSymbolAddress((void**)&dg_x3, g_x3);

    const int NB_SCAN = (NN + 1023) / 1024;   // 98

    k_build<<<(ETOT + 255) / 256, 256>>>(edges);
    k_scan<<<NB_SCAN, 1024>>>();
    k_scatter<<<(ETOT + 255) / 256, 256>>>(edges);

    const int TGRID = (NN + 63) / 64;          // 1563 blocks of 256 (64 nodes each)
    const int AGRID = (NN * 32 + 255) / 256;   // warp per node

    // layer 1: F_IN=16 -> 64 concat + ELU
    k_transform<16><<<TGRID, 256>>>(x, W1, a1s, a1d, dg_h, dg_as, dg_ad);
    k_agg<0><<<AGRID, 256>>>(dg_h, dg_as, dg_ad, b1, dg_x1);
    // layer 2: 64 -> head-mean 16 + ELU
    k_transform<64><<<TGRID, 256>>>(dg_x1, W2, a2s, a2d, dg_h, dg_as, dg_ad);
    k_agg<1><<<AGRID, 256>>>(dg_h, dg_as, dg_ad, b2, dg_x2);
    // layer 3: 16 -> head-mean 16 (no ELU)
    k_transform<16><<<TGRID, 256>>>(dg_x2, W3, a3s, a3d, dg_h, dg_as, dg_ad);
    k_agg<2><<<AGRID, 256>>>(dg_h, dg_as, dg_ad, b3, dg_x3);

    // pooling (+ deg reset) + MLP (+ pool reset)
    k_pool<<<NB_SCAN, 256>>>(batch, edges);
    k_mlp<<<1, 1024>>>(stats, fw1, fb1, fw2, fb2, fw3, fb3, out);
}

// round 13
// speedup vs baseline: 1.4691x; 1.4691x over previous
#include <cuda_runtime.h>
#include <cuda_fp16.h>
#include <cstdint>

#define NN 100000
#define EE 1600000
#define ETOT (EE + NN)
#define BB 64

// ---------------- device scratch (static: no allocs allowed) ----------------
__device__ int    g_is64;
__device__ int    g_esrc[ETOT];
__device__ int    g_edst[ETOT];
__device__ int    g_deg[NN];          // zero-initialized; scan1 re-zeroes after read
__device__ int    g_off[NN + 1];
__device__ int    g_cursor[NN];
__device__ int    g_csr[ETOT];
__device__ int    g_bsum[128];
__device__ __half g_h16[NN * 64];     // fp16 gather payload (softmax weights stay fp32)
__device__ float  g_as[NN * 4];
__device__ float  g_ad[NN * 4];
__device__ float  g_x1[NN * 64];
__device__ float  g_x2[NN * 16];
__device__ float  g_x3[NN * 16];
__device__ float  g_pool[BB * 16];    // zero-initialized; k_mlp re-zeroes after read
__device__ float  g_cnt[BB];

// load 4 contiguous halves as float4 with a single LDG.64
__device__ __forceinline__ float4 ldh4(const __half* p) {
    uint2 r = *(const uint2*)p;
    __half2 h0 = *reinterpret_cast<__half2*>(&r.x);
    __half2 h1 = *reinterpret_cast<__half2*>(&r.y);
    float2 f0 = __half22float2(h0), f1 = __half22float2(h1);
    return make_float4(f0.x, f0.y, f1.x, f1.y);
}

// ------------- init: dtype detection only (1 warp) -------------
__global__ void k_init(const int* e) {
    if (threadIdx.x == 0) {
        int z = 0;
        for (int j = 0; j < 64; j++) z |= e[2 * j + 1];   // high words if int64
        g_is64 = (z == 0) ? 1 : 0;
    }
}

// build edge arrays (+ self loops) and histogram dst
__global__ void k_build(const void* ep) {
    int i = blockIdx.x * blockDim.x + threadIdx.x;
    if (i >= ETOT) return;
    int s, d;
    if (i < EE) {
        if (g_is64) {
            const long long* e = (const long long*)ep;
            s = (int)e[i]; d = (int)e[EE + i];
        } else {
            const int* e = (const int*)ep;
            s = e[i]; d = e[EE + i];
        }
    } else {
        s = d = i - EE;    // self loop
    }
    g_esrc[i] = s;
    g_edst[i] = d;
    atomicAdd(&g_deg[d], 1);
}

// ------------- scan stage 1: per-block exclusive scan + re-zero g_deg -------------
__global__ void k_scan1() {
    __shared__ int warp_sums[32];
    int bid = blockIdx.x, tid = threadIdx.x;
    int i = bid * 1024 + tid;
    int v = 0;
    if (i < NN) { v = g_deg[i]; g_deg[i] = 0; }   // consume + reset for next replay
    int lane = tid & 31, wid = tid >> 5;
    int x = v;
#pragma unroll
    for (int o = 1; o < 32; o <<= 1) {
        int y = __shfl_up_sync(0xffffffffu, x, o);
        if (lane >= o) x += y;
    }
    if (lane == 31) warp_sums[wid] = x;
    __syncthreads();
    if (wid == 0) {
        int s = warp_sums[lane];
#pragma unroll
        for (int o = 1; o < 32; o <<= 1) {
            int y = __shfl_up_sync(0xffffffffu, s, o);
            if (lane >= o) s += y;
        }
        warp_sums[lane] = s;
    }
    __syncthreads();
    int excl = x - v + (wid > 0 ? warp_sums[wid - 1] : 0);
    if (i < NN) g_off[i] = excl;
    if (tid == 1023) g_bsum[bid] = excl + v;
}

// ------------- scan stage 2 (fused): each block redundantly sums its prefix -------------
__global__ void k_scan3() {
    __shared__ int carry_s;
    int tid = threadIdx.x;
    if (tid < 32) {
        int bid = blockIdx.x;
        int carry = 0;
        for (int base = 0; base < bid; base += 32) {
            int idx = base + tid;
            int v = (idx < bid) ? g_bsum[idx] : 0;
#pragma unroll
            for (int o = 16; o >= 1; o >>= 1) v += __shfl_xor_sync(0xffffffffu, v, o);
            carry += v;
        }
        if (tid == 0) carry_s = carry;
    }
    __syncthreads();
    int carry = carry_s;
    int i = blockIdx.x * 1024 + tid;
    if (i < NN) {
        int o = g_off[i] + carry;
        g_off[i] = o;
        g_cursor[i] = o;
    }
    if (blockIdx.x == gridDim.x - 1 && tid == 0)
        g_off[NN] = carry + g_bsum[gridDim.x - 1];
}

__global__ void k_scatter() {
    int i = blockIdx.x * blockDim.x + threadIdx.x;
    if (i >= ETOT) return;
    int d = g_edst[i];
    int p = atomicAdd(&g_cursor[d], 1);
    g_csr[p] = g_esrc[i];
}

// ---------------- transform: k4-vectorized, 4 channels x 4 nodes per thread ----------------
// Per 4 k-steps: 4 LDS.128 (x, one per node, spanning k4..k4+3) + 4 LDS.128 (W)
// + 64 FFMA ~= 1.17 instr/FMA (was 1.34). Outer loop #pragma unroll 1 keeps the
// live set at ~50 regs (the R10 full-unroll variant of this shape spilled).
template <int FIN>
__global__ void k_transform(const float* __restrict__ x, const float* __restrict__ W,
                            const float* __restrict__ a_s, const float* __restrict__ a_d,
                            __half* __restrict__ hout, float* __restrict__ aso,
                            float* __restrict__ ado) {
    constexpr int NODES = 64;
    __shared__ float Ws[FIN * 64];          // [k][64]
    __shared__ float xs[NODES * FIN];       // [node][FIN]
    int tid = threadIdx.x;
    for (int k = tid; k < FIN * 64; k += 256) Ws[k] = W[k];
    long long xbase = (long long)blockIdx.x * NODES * FIN;
    for (int m = tid; m < NODES * FIN; m += 256) {
        long long gi = xbase + m;
        xs[m] = (gi < (long long)NN * FIN) ? x[gi] : 0.f;
    }
    __syncthreads();

    int tj = tid & 15;          // channel group: channels tj*4 .. tj*4+3
    int tn = tid >> 4;          // node slot: nodes g*16+tn
    int j4 = tj * 4;

    float4 acc[4];
#pragma unroll
    for (int g = 0; g < 4; g++) acc[g] = make_float4(0.f, 0.f, 0.f, 0.f);

#pragma unroll 1
    for (int k4 = 0; k4 < FIN; k4 += 4) {
        float xv[4][4];
#pragma unroll
        for (int g = 0; g < 4; g++) {
            float4 t = *(const float4*)&xs[(g * 16 + tn) * FIN + k4];
            xv[g][0] = t.x; xv[g][1] = t.y; xv[g][2] = t.z; xv[g][3] = t.w;
        }
#pragma unroll
        for (int kk = 0; kk < 4; kk++) {
            float4 wv = *(const float4*)&Ws[(k4 + kk) * 64 + j4];
#pragma unroll
            for (int g = 0; g < 4; g++) {
                float xk = xv[g][kk];
                acc[g].x += xk * wv.x;
                acc[g].y += xk * wv.y;
                acc[g].z += xk * wv.z;
                acc[g].w += xk * wv.w;
            }
        }
    }

    // attention partials: this thread's 4 channels all lie in head = tj>>2
    float4 asv = __ldg((const float4*)(a_s + j4));
    float4 adv = __ldg((const float4*)(a_d + j4));
    int nblock = blockIdx.x * NODES;
#pragma unroll
    for (int g = 0; g < 4; g++) {
        int n = nblock + g * 16 + tn;
        float ps = acc[g].x * asv.x + acc[g].y * asv.y + acc[g].z * asv.z + acc[g].w * asv.w;
        float pd = acc[g].x * adv.x + acc[g].y * adv.y + acc[g].z * adv.z + acc[g].w * adv.w;
        ps += __shfl_xor_sync(0xffffffffu, ps, 1);
        ps += __shfl_xor_sync(0xffffffffu, ps, 2);
        pd += __shfl_xor_sync(0xffffffffu, pd, 1);
        pd += __shfl_xor_sync(0xffffffffu, pd, 2);
        if ((tj & 3) == 0 && n < NN) {
            int head = tj >> 2;
            aso[n * 4 + head] = ps;
            ado[n * 4 + head] = pd;
        }
        if (n < NN) {
            __half2 lo = __floats2half2_rn(acc[g].x, acc[g].y);
            __half2 hi = __floats2half2_rn(acc[g].z, acc[g].w);
            uint2 pk;
            pk.x = *reinterpret_cast<unsigned int*>(&lo);
            pk.y = *reinterpret_cast<unsigned int*>(&hi);
            *(uint2*)(hout + n * 64 + j4) = pk;
        }
    }
}

// ---------------- warp-per-destination softmax aggregation (fp16 payload) ----------------
// MODE 0: concat (64) + bias + ELU ; 1: head-mean + bias + ELU ; 2: head-mean + bias.
template <int MODE>
__global__ void k_agg(const __half* __restrict__ h, const float* __restrict__ as_,
                      const float* __restrict__ ad_, const float* __restrict__ bias,
                      float* __restrict__ out) {
    int w = (blockIdx.x * blockDim.x + threadIdx.x) >> 5;
    if (w >= NN) return;
    int lane = threadIdx.x & 31;
    int half_ = lane >> 4;         // which edge of the pair
    int q = lane & 15;             // channel group: channels q*4..q*4+3
    int head = q >> 2;
    float adh = __ldg(&ad_[w * 4 + head]);
    float den = 0.f;
    float4 acc = make_float4(0.f, 0.f, 0.f, 0.f);
    int s0 = __ldg(&g_off[w]), s1 = __ldg(&g_off[w + 1]);
    int last = s1 - 1;             // degree >= 1 (self loop)
    for (int i = s0; i < s1; i += 4) {
        int ia = i + half_;
        int ib = i + 2 + half_;
        bool va = ia < s1, vb = ib < s1;
        int sa = __ldg(&g_csr[min(ia, last)]);
        int sb = __ldg(&g_csr[min(ib, last)]);
        float ea = __ldg(&as_[sa * 4 + head]);
        float eb = __ldg(&as_[sb * 4 + head]);
        float4 ha = ldh4(h + sa * 64 + q * 4);
        float4 hb = ldh4(h + sb * 64 + q * 4);
        ea += adh; ea = ea > 0.f ? ea : 0.2f * ea;
        eb += adh; eb = eb > 0.f ? eb : 0.2f * eb;
        float wa = va ? __expf(ea) : 0.f;
        float wb = vb ? __expf(eb) : 0.f;
        den += wa + wb;
        acc.x += wa * ha.x + wb * hb.x;
        acc.y += wa * ha.y + wb * hb.y;
        acc.z += wa * ha.z + wb * hb.z;
        acc.w += wa * ha.w + wb * hb.w;
    }
    den   += __shfl_xor_sync(0xffffffffu, den,   16);
    acc.x += __shfl_xor_sync(0xffffffffu, acc.x, 16);
    acc.y += __shfl_xor_sync(0xffffffffu, acc.y, 16);
    acc.z += __shfl_xor_sync(0xffffffffu, acc.z, 16);
    acc.w += __shfl_xor_sync(0xffffffffu, acc.w, 16);
    float inv = 1.f / den;
    float4 o4;
    o4.x = acc.x * inv; o4.y = acc.y * inv; o4.z = acc.z * inv; o4.w = acc.w * inv;
    if (MODE == 0) {
        if (half_ == 0) {
            float4 b4 = __ldg((const float4*)(bias + q * 4));
            o4.x += b4.x; o4.y += b4.y; o4.z += b4.z; o4.w += b4.w;
            o4.x = o4.x > 0.f ? o4.x : expm1f(o4.x);
            o4.y = o4.y > 0.f ? o4.y : expm1f(o4.y);
            o4.z = o4.z > 0.f ? o4.z : expm1f(o4.z);
            o4.w = o4.w > 0.f ? o4.w : expm1f(o4.w);
            *(float4*)(out + w * 64 + q * 4) = o4;
        }
    } else {
#pragma unroll
        for (int o = 4; o <= 8; o <<= 1) {
            o4.x += __shfl_xor_sync(0xffffffffu, o4.x, o);
            o4.y += __shfl_xor_sync(0xffffffffu, o4.y, o);
            o4.z += __shfl_xor_sync(0xffffffffu, o4.z, o);
            o4.w += __shfl_xor_sync(0xffffffffu, o4.w, o);
        }
        if (half_ == 0 && q < 4) {
            float4 b4 = __ldg((const float4*)(bias + q * 4));
            float4 v;
            v.x = 0.25f * o4.x + b4.x;
            v.y = 0.25f * o4.y + b4.y;
            v.z = 0.25f * o4.z + b4.z;
            v.w = 0.25f * o4.w + b4.w;
            if (MODE == 1) {
                v.x = v.x > 0.f ? v.x : expm1f(v.x);
                v.y = v.y > 0.f ? v.y : expm1f(v.y);
                v.z = v.z > 0.f ? v.z : expm1f(v.z);
                v.w = v.w > 0.f ? v.w : expm1f(v.w);
            }
            *(float4*)(out + w * 16 + q * 4) = v;
        }
    }
}

// --------- mean pooling: batch is sorted -> run-length local accumulation ---------
__global__ void k_pool(const void* bp) {
    constexpr int NPB = 1024;           // nodes per block
    int c = threadIdx.x & 15;
    int nrel = threadIdx.x >> 4;        // 0..15
    int base = blockIdx.x * NPB;
    float acc = 0.f, cnt = 0.f;
    int bcur = -1;
    for (int k = 0; k < NPB / 16; k++) {
        int n = base + k * 16 + nrel;
        if (n >= NN) break;
        int b = g_is64 ? (int)((const long long*)bp)[n] : ((const int*)bp)[n];
        if (b != bcur) {
            if (bcur >= 0) {
                atomicAdd(&g_pool[bcur * 16 + c], acc);
                if (c == 0) atomicAdd(&g_cnt[bcur], cnt);
            }
            bcur = b; acc = 0.f; cnt = 0.f;
        }
        acc += g_x3[n * 16 + c];
        cnt += 1.f;
    }
    if (bcur >= 0) {
        atomicAdd(&g_pool[bcur * 16 + c], acc);
        if (c == 0) atomicAdd(&g_cnt[bcur], cnt);
    }
}

// ---------------- tiny MLP head (single block) — also resets pool state ----------------
__global__ void k_mlp(const float* __restrict__ stats,
                      const float* __restrict__ fw1, const float* __restrict__ fb1,
                      const float* __restrict__ fw2, const float* __restrict__ fb2,
                      const float* __restrict__ fw3, const float* __restrict__ fb3,
                      float* __restrict__ out) {
    __shared__ float zin[BB * 32];
    __shared__ float z1[BB * 32];
    __shared__ float z2[BB * 16];
    int tid = threadIdx.x;
    for (int t = tid; t < BB * 32; t += blockDim.x) {
        int b = t >> 5, k = t & 31;
        zin[t] = (k < 16) ? g_pool[b * 16 + k] / fmaxf(g_cnt[b], 1.f)
                          : stats[b * 16 + (k - 16)];
    }
    __syncthreads();
    // reset pool accumulators for the next graph replay (deterministic invariant)
    if (tid < BB * 16) g_pool[tid] = 0.f;
    if (tid < BB) g_cnt[tid] = 0.f;
    for (int t = tid; t < BB * 32; t += blockDim.x) {
        int b = t >> 5, j = t & 31;
        float a = fb1[j];
#pragma unroll
        for (int k = 0; k < 32; k++) a += zin[b * 32 + k] * fw1[k * 32 + j];
        z1[t] = fmaxf(a, 0.f);
    }
    __syncthreads();
    for (int t = tid; t < BB * 16; t += blockDim.x) {
        int b = t >> 4, j = t & 15;
        float a = fb2[j];
#pragma unroll
        for (int k = 0; k < 32; k++) a += z1[b * 32 + k] * fw2[k * 16 + j];
        z2[t] = fmaxf(a, 0.f);
    }
    __syncthreads();
    for (int t = tid; t < BB; t += blockDim.x) {
        float a = fb3[0];
#pragma unroll
        for (int k = 0; k < 16; k++) a += z2[t * 16 + k] * fw3[k];
        out[t] = a;
    }
}

// ---------------- launcher ----------------
extern "C" void kernel_launch(void* const* d_in, const int* in_sizes, int n_in,
                              void* d_out, int out_size) {
    const float* x     = (const float*)d_in[0];
    const float* stats = (const float*)d_in[1];
    const float* W1  = (const float*)d_in[2];
    const float* a1s = (const float*)d_in[3];
    const float* a1d = (const float*)d_in[4];
    const float* b1  = (const float*)d_in[5];
    const float* W2  = (const float*)d_in[6];
    const float* a2s = (const float*)d_in[7];
    const float* a2d = (const float*)d_in[8];
    const float* b2  = (const float*)d_in[9];
    const float* W3  = (const float*)d_in[10];
    const float* a3s = (const float*)d_in[11];
    const float* a3d = (const float*)d_in[12];
    const float* b3  = (const float*)d_in[13];
    const float* fw1 = (const float*)d_in[14];
    const float* fb1 = (const float*)d_in[15];
    const float* fw2 = (const float*)d_in[16];
    const float* fb2 = (const float*)d_in[17];
    const float* fw3 = (const float*)d_in[18];
    const float* fb3 = (const float*)d_in[19];
    const void*  edges = d_in[20];
    const void*  batch = d_in[21];
    float* out = (float*)d_out;

    __half* dg_h; cudaGetSymbolAddress((void**)&dg_h,  g_h16);
    float* dg_as; cudaGetSymbolAddress((void**)&dg_as, g_as);
    float* dg_ad; cudaGetSymbolAddress((void**)&dg_ad, g_ad);
    float* dg_x1; cudaGetSymbolAddress((void**)&dg_x1, g_x1);
    float* dg_x2; cudaGetSymbolAddress((void**)&dg_x2, g_x2);
    float* dg_x3; cudaGetSymbolAddress((void**)&dg_x3, g_x3);

    const int NB_SCAN = (NN + 1023) / 1024;   // 98

    k_init<<<1, 32>>>((const int*)edges);
    k_build<<<(ETOT + 255) / 256, 256>>>(edges);
    k_scan1<<<NB_SCAN, 1024>>>();
    k_scan3<<<NB_SCAN, 1024>>>();
    k_scatter<<<(ETOT + 255) / 256, 256>>>();

    const int TGRID = (NN + 63) / 64;          // 1563 blocks of 256 (64 nodes each)
    const int AGRID = (NN * 32 + 255) / 256;   // warp per node

    // layer 1: F_IN=16 -> 64 concat + ELU
    k_transform<16><<<TGRID, 256>>>(x, W1, a1s, a1d, dg_h, dg_as, dg_ad);
    k_agg<0><<<AGRID, 256>>>(dg_h, dg_as, dg_ad, b1, dg_x1);
    // layer 2: 64 -> head-mean 16 + ELU
    k_transform<64><<<TGRID, 256>>>(dg_x1, W2, a2s, a2d, dg_h, dg_as, dg_ad);
    k_agg<1><<<AGRID, 256>>>(dg_h, dg_as, dg_ad, b2, dg_x2);
    // layer 3: 16 -> head-mean 16 (no ELU)
    k_transform<16><<<TGRID, 256>>>(dg_x2, W3, a3s, a3d, dg_h, dg_as, dg_ad);
    k_agg<2><<<AGRID, 256>>>(dg_h, dg_as, dg_ad, b3, dg_x3);

    // pooling + MLP
    k_pool<<<(NN + 1023) / 1024, 256>>>(batch);
    k_mlp<<<1, 1024>>>(stats, fw1, fb1, fw2, fb2, fw3, fb3, out);
}

// round 14
// speedup vs baseline: 1.5122x; 1.0293x over previous
#include <cuda_runtime.h>
#include <cuda_fp16.h>
#include <cstdint>

#define NN 100000
#define EE 1600000
#define ETOT (EE + NN)
#define BB 64

// ---------------- device scratch (static: no allocs allowed) ----------------
__device__ int    g_is64;
__device__ int    g_esrc[ETOT];
__device__ int    g_edst[ETOT];
__device__ int    g_deg[NN];          // zero-initialized; k_pool re-zeroes each replay
__device__ int    g_off[NN + 1];
__device__ int    g_cursor[NN];
__device__ int    g_csr[ETOT];
__device__ __half g_h16[NN * 64];     // fp16 gather payload (softmax weights stay fp32)
__device__ float  g_as[NN * 4];
__device__ float  g_ad[NN * 4];
__device__ float  g_x1[NN * 64];
__device__ float  g_x2[NN * 16];
__device__ float  g_x3[NN * 16];
__device__ float  g_pool[BB * 16];    // zero-initialized; k_mlp re-zeroes after read
__device__ float  g_cnt[BB];

// load 4 contiguous halves as float4 with a single LDG.64
__device__ __forceinline__ float4 ldh4(const __half* p) {
    uint2 r = *(const uint2*)p;
    __half2 h0 = *reinterpret_cast<__half2*>(&r.x);
    __half2 h1 = *reinterpret_cast<__half2*>(&r.y);
    float2 f0 = __half22float2(h0), f1 = __half22float2(h1);
    return make_float4(f0.x, f0.y, f1.x, f1.y);
}

// ------------- init: dtype detection only (1 warp) -------------
__global__ void k_init(const int* e) {
    if (threadIdx.x == 0) {
        int z = 0;
        for (int j = 0; j < 64; j++) z |= e[2 * j + 1];   // high words if int64
        g_is64 = (z == 0) ? 1 : 0;
    }
}

// build edge arrays (+ self loops) and histogram dst
__global__ void k_build(const void* ep) {
    int i = blockIdx.x * blockDim.x + threadIdx.x;
    if (i >= ETOT) return;
    int s, d;
    if (i < EE) {
        if (g_is64) {
            const long long* e = (const long long*)ep;
            s = (int)e[i]; d = (int)e[EE + i];
        } else {
            const int* e = (const int*)ep;
            s = e[i]; d = e[EE + i];
        }
    } else {
        s = d = i - EE;    // self loop
    }
    g_esrc[i] = s;
    g_edst[i] = d;
    atomicAdd(&g_deg[d], 1);
}

// ------------- single-kernel exclusive scan (block-redundant prefix) -------------
// Block b: (1) all 1024 threads reduce-sum g_deg[0 .. b*1024) (L2-resident),
// (2) block-scan its own 1024 degrees. g_deg left intact (k_pool resets it).
__global__ void k_scan() {
    __shared__ int warp_sums[32];
    __shared__ int carry_s;
    int bid = blockIdx.x, tid = threadIdx.x;
    int lane = tid & 31, wid = tid >> 5;
    int pre = bid * 1024;

    // ---- carry = sum of all degrees below this block ----
    int c = 0;
    for (int j = tid; j < pre; j += 1024) c += g_deg[j];
#pragma unroll
    for (int o = 16; o >= 1; o >>= 1) c += __shfl_xor_sync(0xffffffffu, c, o);
    if (lane == 0) warp_sums[wid] = c;
    __syncthreads();
    if (wid == 0) {
        int s = warp_sums[lane];
#pragma unroll
        for (int o = 16; o >= 1; o >>= 1) s += __shfl_xor_sync(0xffffffffu, s, o);
        if (lane == 0) carry_s = s;
    }
    __syncthreads();
    int carry = carry_s;
    __syncthreads();   // warp_sums about to be reused

    // ---- exclusive scan of own 1024 degrees ----
    int i = pre + tid;
    int v = (i < NN) ? g_deg[i] : 0;
    int x = v;
#pragma unroll
    for (int o = 1; o < 32; o <<= 1) {
        int y = __shfl_up_sync(0xffffffffu, x, o);
        if (lane >= o) x += y;
    }
    if (lane == 31) warp_sums[wid] = x;
    __syncthreads();
    if (wid == 0) {
        int s = warp_sums[lane];
#pragma unroll
        for (int o = 1; o < 32; o <<= 1) {
            int y = __shfl_up_sync(0xffffffffu, s, o);
            if (lane >= o) s += y;
        }
        warp_sums[lane] = s;
    }
    __syncthreads();
    int excl = x - v + (wid > 0 ? warp_sums[wid - 1] : 0) + carry;
    if (i < NN) {
        g_off[i] = excl;
        g_cursor[i] = excl;
    }
    if (bid == 0 && tid == 0) g_off[NN] = ETOT;   // total is a compile-time constant
}

__global__ void k_scatter() {
    int i = blockIdx.x * blockDim.x + threadIdx.x;
    if (i >= ETOT) return;
    int d = g_edst[i];
    int p = atomicAdd(&g_cursor[d], 1);
    g_csr[p] = g_esrc[i];
}

// ---------------- transform: k4-vectorized, 4 channels x 4 nodes per thread ----------------
// __launch_bounds__(256, 6): cap regs at 42 -> ~75% occupancy (was 48 regs/55%).
// Theory: two mainloop shapes measured identical 26us -> latency-exposure bound,
// so more resident warps should shrink it.
template <int FIN>
__global__ void __launch_bounds__(256, 6)
k_transform(const float* __restrict__ x, const float* __restrict__ W,
            const float* __restrict__ a_s, const float* __restrict__ a_d,
            __half* __restrict__ hout, float* __restrict__ aso,
            float* __restrict__ ado) {
    constexpr int NODES = 64;
    __shared__ float Ws[FIN * 64];          // [k][64]
    __shared__ float xs[NODES * FIN];       // [node][FIN]
    int tid = threadIdx.x;
    for (int k = tid; k < FIN * 64; k += 256) Ws[k] = W[k];
    long long xbase = (long long)blockIdx.x * NODES * FIN;
    for (int m = tid; m < NODES * FIN; m += 256) {
        long long gi = xbase + m;
        xs[m] = (gi < (long long)NN * FIN) ? x[gi] : 0.f;
    }
    __syncthreads();

    int tj = tid & 15;          // channel group: channels tj*4 .. tj*4+3
    int tn = tid >> 4;          // node slot: nodes g*16+tn
    int j4 = tj * 4;

    float4 acc[4];
#pragma unroll
    for (int g = 0; g < 4; g++) acc[g] = make_float4(0.f, 0.f, 0.f, 0.f);

#pragma unroll 1
    for (int k4 = 0; k4 < FIN; k4 += 4) {
        float xv[4][4];
#pragma unroll
        for (int g = 0; g < 4; g++) {
            float4 t = *(const float4*)&xs[(g * 16 + tn) * FIN + k4];
            xv[g][0] = t.x; xv[g][1] = t.y; xv[g][2] = t.z; xv[g][3] = t.w;
        }
#pragma unroll
        for (int kk = 0; kk < 4; kk++) {
            float4 wv = *(const float4*)&Ws[(k4 + kk) * 64 + j4];
#pragma unroll
            for (int g = 0; g < 4; g++) {
                float xk = xv[g][kk];
                acc[g].x += xk * wv.x;
                acc[g].y += xk * wv.y;
                acc[g].z += xk * wv.z;
                acc[g].w += xk * wv.w;
            }
        }
    }

    // attention partials: this thread's 4 channels all lie in head = tj>>2
    float4 asv = __ldg((const float4*)(a_s + j4));
    float4 adv = __ldg((const float4*)(a_d + j4));
    int nblock = blockIdx.x * NODES;
#pragma unroll
    for (int g = 0; g < 4; g++) {
        int n = nblock + g * 16 + tn;
        float ps = acc[g].x * asv.x + acc[g].y * asv.y + acc[g].z * asv.z + acc[g].w * asv.w;
        float pd = acc[g].x * adv.x + acc[g].y * adv.y + acc[g].z * adv.z + acc[g].w * adv.w;
        ps += __shfl_xor_sync(0xffffffffu, ps, 1);
        ps += __shfl_xor_sync(0xffffffffu, ps, 2);
        pd += __shfl_xor_sync(0xffffffffu, pd, 1);
        pd += __shfl_xor_sync(0xffffffffu, pd, 2);
        if ((tj & 3) == 0 && n < NN) {
            int head = tj >> 2;
            aso[n * 4 + head] = ps;
            ado[n * 4 + head] = pd;
        }
        if (n < NN) {
            __half2 lo = __floats2half2_rn(acc[g].x, acc[g].y);
            __half2 hi = __floats2half2_rn(acc[g].z, acc[g].w);
            uint2 pk;
            pk.x = *reinterpret_cast<unsigned int*>(&lo);
            pk.y = *reinterpret_cast<unsigned int*>(&hi);
            *(uint2*)(hout + n * 64 + j4) = pk;
        }
    }
}

// ---------------- warp-per-destination softmax aggregation (fp16 payload) ----------------
// MODE 0: concat (64) + bias + ELU ; 1: head-mean + bias + ELU ; 2: head-mean + bias.
template <int MODE>
__global__ void k_agg(const __half* __restrict__ h, const float* __restrict__ as_,
                      const float* __restrict__ ad_, const float* __restrict__ bias,
                      float* __restrict__ out) {
    int w = (blockIdx.x * blockDim.x + threadIdx.x) >> 5;
    if (w >= NN) return;
    int lane = threadIdx.x & 31;
    int half_ = lane >> 4;         // which edge of the pair
    int q = lane & 15;             // channel group: channels q*4..q*4+3
    int head = q >> 2;
    float adh = __ldg(&ad_[w * 4 + head]);
    float den = 0.f;
    float4 acc = make_float4(0.f, 0.f, 0.f, 0.f);
    int s0 = __ldg(&g_off[w]), s1 = __ldg(&g_off[w + 1]);
    int last = s1 - 1;             // degree >= 1 (self loop)
    for (int i = s0; i < s1; i += 4) {
        int ia = i + half_;
        int ib = i + 2 + half_;
        bool va = ia < s1, vb = ib < s1;
        int sa = __ldg(&g_csr[min(ia, last)]);
        int sb = __ldg(&g_csr[min(ib, last)]);
        float ea = __ldg(&as_[sa * 4 + head]);
        float eb = __ldg(&as_[sb * 4 + head]);
        float4 ha = ldh4(h + sa * 64 + q * 4);
        float4 hb = ldh4(h + sb * 64 + q * 4);
        ea += adh; ea = ea > 0.f ? ea : 0.2f * ea;
        eb += adh; eb = eb > 0.f ? eb : 0.2f * eb;
        float wa = va ? __expf(ea) : 0.f;
        float wb = vb ? __expf(eb) : 0.f;
        den += wa + wb;
        acc.x += wa * ha.x + wb * hb.x;
        acc.y += wa * ha.y + wb * hb.y;
        acc.z += wa * ha.z + wb * hb.z;
        acc.w += wa * ha.w + wb * hb.w;
    }
    den   += __shfl_xor_sync(0xffffffffu, den,   16);
    acc.x += __shfl_xor_sync(0xffffffffu, acc.x, 16);
    acc.y += __shfl_xor_sync(0xffffffffu, acc.y, 16);
    acc.z += __shfl_xor_sync(0xffffffffu, acc.z, 16);
    acc.w += __shfl_xor_sync(0xffffffffu, acc.w, 16);
    float inv = 1.f / den;
    float4 o4;
    o4.x = acc.x * inv; o4.y = acc.y * inv; o4.z = acc.z * inv; o4.w = acc.w * inv;
    if (MODE == 0) {
        if (half_ == 0) {
            float4 b4 = __ldg((const float4*)(bias + q * 4));
            o4.x += b4.x; o4.y += b4.y; o4.z += b4.z; o4.w += b4.w;
            o4.x = o4.x > 0.f ? o4.x : expm1f(o4.x);
            o4.y = o4.y > 0.f ? o4.y : expm1f(o4.y);
            o4.z = o4.z > 0.f ? o4.z : expm1f(o4.z);
            o4.w = o4.w > 0.f ? o4.w : expm1f(o4.w);
            *(float4*)(out + w * 64 + q * 4) = o4;
        }
    } else {
#pragma unroll
        for (int o = 4; o <= 8; o <<= 1) {
            o4.x += __shfl_xor_sync(0xffffffffu, o4.x, o);
            o4.y += __shfl_xor_sync(0xffffffffu, o4.y, o);
            o4.z += __shfl_xor_sync(0xffffffffu, o4.z, o);
            o4.w += __shfl_xor_sync(0xffffffffu, o4.w, o);
        }
        if (half_ == 0 && q < 4) {
            float4 b4 = __ldg((const float4*)(bias + q * 4));
            float4 v;
            v.x = 0.25f * o4.x + b4.x;
            v.y = 0.25f * o4.y + b4.y;
            v.z = 0.25f * o4.z + b4.z;
            v.w = 0.25f * o4.w + b4.w;
            if (MODE == 1) {
                v.x = v.x > 0.f ? v.x : expm1f(v.x);
                v.y = v.y > 0.f ? v.y : expm1f(v.y);
                v.z = v.z > 0.f ? v.z : expm1f(v.z);
                v.w = v.w > 0.f ? v.w : expm1f(v.w);
            }
            *(float4*)(out + w * 16 + q * 4) = v;
        }
    }
}

// --------- mean pooling (sorted batch -> run-length) + re-zero g_deg slice ---------
__global__ void k_pool(const void* bp) {
    constexpr int NPB = 1024;           // nodes per block
    // reset this block's degree-histogram slice for the next replay
    for (int j = threadIdx.x; j < NPB; j += blockDim.x) {
        int n = blockIdx.x * NPB + j;
        if (n < NN) g_deg[n] = 0;
    }
    int c = threadIdx.x & 15;
    int nrel = threadIdx.x >> 4;        // 0..15
    int base = blockIdx.x * NPB;
    float acc = 0.f, cnt = 0.f;
    int bcur = -1;
    for (int k = 0; k < NPB / 16; k++) {
        int n = base + k * 16 + nrel;
        if (n >= NN) break;
        int b = g_is64 ? (int)((const long long*)bp)[n] : ((const int*)bp)[n];
        if (b != bcur) {
            if (bcur >= 0) {
                atomicAdd(&g_pool[bcur * 16 + c], acc);
                if (c == 0) atomicAdd(&g_cnt[bcur], cnt);
            }
            bcur = b; acc = 0.f; cnt = 0.f;
        }
        acc += g_x3[n * 16 + c];
        cnt += 1.f;
    }
    if (bcur >= 0) {
        atomicAdd(&g_pool[bcur * 16 + c], acc);
        if (c == 0) atomicAdd(&g_cnt[bcur], cnt);
    }
}

// ---------------- tiny MLP head (single block) — also resets pool state ----------------
__global__ void k_mlp(const float* __restrict__ stats,
                      const float* __restrict__ fw1, const float* __restrict__ fb1,
                      const float* __restrict__ fw2, const float* __restrict__ fb2,
                      const float* __restrict__ fw3, const float* __restrict__ fb3,
                      float* __restrict__ out) {
    __shared__ float zin[BB * 32];
    __shared__ float z1[BB * 32];
    __shared__ float z2[BB * 16];
    int tid = threadIdx.x;
    for (int t = tid; t < BB * 32; t += blockDim.x) {
        int b = t >> 5, k = t & 31;
        zin[t] = (k < 16) ? g_pool[b * 16 + k] / fmaxf(g_cnt[b], 1.f)
                          : stats[b * 16 + (k - 16)];
    }
    __syncthreads();
    // reset pool accumulators for the next graph replay (deterministic invariant)
    if (tid < BB * 16) g_pool[tid] = 0.f;
    if (tid < BB) g_cnt[tid] = 0.f;
    for (int t = tid; t < BB * 32; t += blockDim.x) {
        int b = t >> 5, j = t & 31;
        float a = fb1[j];
#pragma unroll
        for (int k = 0; k < 32; k++) a += zin[b * 32 + k] * fw1[k * 32 + j];
        z1[t] = fmaxf(a, 0.f);
    }
    __syncthreads();
    for (int t = tid; t < BB * 16; t += blockDim.x) {
        int b = t >> 4, j = t & 15;
        float a = fb2[j];
#pragma unroll
        for (int k = 0; k < 32; k++) a += z1[b * 32 + k] * fw2[k * 16 + j];
        z2[t] = fmaxf(a, 0.f);
    }
    __syncthreads();
    for (int t = tid; t < BB; t += blockDim.x) {
        float a = fb3[0];
#pragma unroll
        for (int k = 0; k < 16; k++) a += z2[t * 16 + k] * fw3[k];
        out[t] = a;
    }
}

// ---------------- launcher ----------------
extern "C" void kernel_launch(void* const* d_in, const int* in_sizes, int n_in,
                              void* d_out, int out_size) {
    const float* x     = (const float*)d_in[0];
    const float* stats = (const float*)d_in[1];
    const float* W1  = (const float*)d_in[2];
    const float* a1s = (const float*)d_in[3];
    const float* a1d = (const float*)d_in[4];
    const float* b1  = (const float*)d_in[5];
    const float* W2  = (const float*)d_in[6];
    const float* a2s = (const float*)d_in[7];
    const float* a2d = (const float*)d_in[8];
    const float* b2  = (const float*)d_in[9];
    const float* W3  = (const float*)d_in[10];
    const float* a3s = (const float*)d_in[11];
    const float* a3d = (const float*)d_in[12];
    const float* b3  = (const float*)d_in[13];
    const float* fw1 = (const float*)d_in[14];
    const float* fb1 = (const float*)d_in[15];
    const float* fw2 = (const float*)d_in[16];
    const float* fb2 = (const float*)d_in[17];
    const float* fw3 = (const float*)d_in[18];
    const float* fb3 = (const float*)d_in[19];
    const void*  edges = d_in[20];
    const void*  batch = d_in[21];
    float* out = (float*)d_out;

    __half* dg_h; cudaGetSymbolAddress((void**)&dg_h,  g_h16);
    float* dg_as; cudaGetSymbolAddress((void**)&dg_as, g_as);
    float* dg_ad; cudaGetSymbolAddress((void**)&dg_ad, g_ad);
    float* dg_x1; cudaGetSymbolAddress((void**)&dg_x1, g_x1);
    float* dg_x2; cudaGetSymbolAddress((void**)&dg_x2, g_x2);
    float* dg_x3; cudaGetSymbolAddress((void**)&dg_x3, g_x3);

    const int NB_SCAN = (NN + 1023) / 1024;   // 98
    const int TGRID = (NN + 63) / 64;          // 1563 blocks of 256 (64 nodes each)
    const int AGRID = (NN * 32 + 255) / 256;   // warp per node

    // Launch order puts t16 (graph-independent) at index 3 — the launch ncu
    // consistently captures — so this round's transform change gets profiled.
    k_init<<<1, 32>>>((const int*)edges);                              // 0
    k_build<<<(ETOT + 255) / 256, 256>>>(edges);                       // 1
    k_scan<<<NB_SCAN, 1024>>>();                                       // 2
    k_transform<16><<<TGRID, 256>>>(x, W1, a1s, a1d, dg_h, dg_as, dg_ad); // 3 (profiled)
    k_scatter<<<(ETOT + 255) / 256, 256>>>();                          // 4

    // layer 1 aggregation: concat + ELU
    k_agg<0><<<AGRID, 256>>>(dg_h, dg_as, dg_ad, b1, dg_x1);           // 5
    // layer 2: 64 -> head-mean 16 + ELU
    k_transform<64><<<TGRID, 256>>>(dg_x1, W2, a2s, a2d, dg_h, dg_as, dg_ad); // 6
    k_agg<1><<<AGRID, 256>>>(dg_h, dg_as, dg_ad, b2, dg_x2);           // 7
    // layer 3: 16 -> head-mean 16 (no ELU)
    k_transform<16><<<TGRID, 256>>>(dg_x2, W3, a3s, a3d, dg_h, dg_as, dg_ad); // 8
    k_agg<2><<<AGRID, 256>>>(dg_h, dg_as, dg_ad, b3, dg_x3);           // 9

    // pooling (+ deg reset) + MLP (+ pool reset)
    k_pool<<<NB_SCAN, 256>>>(batch);                                   // 10
    k_mlp<<<1, 1024>>>(stats, fw1, fb1, fw2, fb2, fw3, fb3, out);      // 11
}

// round 15
// speedup vs baseline: 1.5407x; 1.0188x over previous
#include <cuda_runtime.h>
#include <cuda_fp16.h>
#include <cstdint>

#define NN 100000
#define EE 1600000
#define ETOT (EE + NN)
#define BB 64

// ---------------- device scratch (static: no allocs allowed) ----------------
__device__ int    g_is64;
__device__ int    g_esrc[ETOT];
__device__ int    g_edst[ETOT];
__device__ int    g_deg[NN];          // zero-initialized; k_pool re-zeroes each replay
__device__ int    g_off[NN + 1];
__device__ int    g_cursor[NN];
__device__ int    g_csr[ETOT];
__device__ __half g_h16[NN * 64];     // fp16 gather payload (softmax weights stay fp32)
__device__ float  g_as[NN * 4];       // logits pre-scaled by log2(e)
__device__ float  g_ad[NN * 4];
__device__ float  g_x1[NN * 64];
__device__ float  g_x2[NN * 16];
__device__ float  g_x3[NN * 16];
__device__ float  g_pool[BB * 16];    // zero-initialized; k_mlp re-zeroes after read
__device__ float  g_cnt[BB];

#define LOG2E 1.4426950408889634f

__device__ __forceinline__ float ex2f(float x) {
    float r; asm("ex2.approx.f32 %0, %1;" : "=f"(r) : "f"(x)); return r;
}

// load 4 contiguous halves as float4 with a single LDG.64
__device__ __forceinline__ float4 ldh4(const __half* p) {
    uint2 r = *(const uint2*)p;
    __half2 h0 = *reinterpret_cast<__half2*>(&r.x);
    __half2 h1 = *reinterpret_cast<__half2*>(&r.y);
    float2 f0 = __half22float2(h0), f1 = __half22float2(h1);
    return make_float4(f0.x, f0.y, f1.x, f1.y);
}

// ------------- init: dtype detection only (1 warp) -------------
__global__ void k_init(const int* e) {
    if (threadIdx.x == 0) {
        int z = 0;
        for (int j = 0; j < 64; j++) z |= e[2 * j + 1];   // high words if int64
        g_is64 = (z == 0) ? 1 : 0;
    }
}

// build edge arrays (+ self loops) and histogram dst
__global__ void k_build(const void* ep) {
    int i = blockIdx.x * blockDim.x + threadIdx.x;
    if (i >= ETOT) return;
    int s, d;
    if (i < EE) {
        if (g_is64) {
            const long long* e = (const long long*)ep;
            s = (int)e[i]; d = (int)e[EE + i];
        } else {
            const int* e = (const int*)ep;
            s = e[i]; d = e[EE + i];
        }
    } else {
        s = d = i - EE;    // self loop
    }
    g_esrc[i] = s;
    g_edst[i] = d;
    atomicAdd(&g_deg[d], 1);
}

// ------------- single-kernel exclusive scan (block-redundant prefix) -------------
__global__ void k_scan() {
    __shared__ int warp_sums[32];
    __shared__ int carry_s;
    int bid = blockIdx.x, tid = threadIdx.x;
    int lane = tid & 31, wid = tid >> 5;
    int pre = bid * 1024;

    int c = 0;
    for (int j = tid; j < pre; j += 1024) c += g_deg[j];
#pragma unroll
    for (int o = 16; o >= 1; o >>= 1) c += __shfl_xor_sync(0xffffffffu, c, o);
    if (lane == 0) warp_sums[wid] = c;
    __syncthreads();
    if (wid == 0) {
        int s = warp_sums[lane];
#pragma unroll
        for (int o = 16; o >= 1; o >>= 1) s += __shfl_xor_sync(0xffffffffu, s, o);
        if (lane == 0) carry_s = s;
    }
    __syncthreads();
    int carry = carry_s;
    __syncthreads();

    int i = pre + tid;
    int v = (i < NN) ? g_deg[i] : 0;
    int x = v;
#pragma unroll
    for (int o = 1; o < 32; o <<= 1) {
        int y = __shfl_up_sync(0xffffffffu, x, o);
        if (lane >= o) x += y;
    }
    if (lane == 31) warp_sums[wid] = x;
    __syncthreads();
    if (wid == 0) {
        int s = warp_sums[lane];
#pragma unroll
        for (int o = 1; o < 32; o <<= 1) {
            int y = __shfl_up_sync(0xffffffffu, s, o);
            if (lane >= o) s += y;
        }
        warp_sums[lane] = s;
    }
    __syncthreads();
    int excl = x - v + (wid > 0 ? warp_sums[wid - 1] : 0) + carry;
    if (i < NN) {
        g_off[i] = excl;
        g_cursor[i] = excl;
    }
    if (bid == 0 && tid == 0) g_off[NN] = ETOT;
}

__global__ void k_scatter() {
    int i = blockIdx.x * blockDim.x + threadIdx.x;
    if (i >= ETOT) return;
    int d = g_edst[i];
    int p = atomicAdd(&g_cursor[d], 1);
    g_csr[p] = g_esrc[i];
}

// ---------------- transform: k4-vectorized, 4 channels x 4 nodes per thread ----------------
// __launch_bounds__(256,6): 40 regs, ~64% occ (verified R14: 26.3 -> 16.6us).
// Logits written pre-scaled by log2(e) so agg can use raw ex2.approx.
template <int FIN>
__global__ void __launch_bounds__(256, 6)
k_transform(const float* __restrict__ x, const float* __restrict__ W,
            const float* __restrict__ a_s, const float* __restrict__ a_d,
            __half* __restrict__ hout, float* __restrict__ aso,
            float* __restrict__ ado) {
    constexpr int NODES = 64;
    __shared__ float Ws[FIN * 64];          // [k][64]
    __shared__ float xs[NODES * FIN];       // [node][FIN]
    int tid = threadIdx.x;
    for (int k = tid; k < FIN * 64; k += 256) Ws[k] = W[k];
    long long xbase = (long long)blockIdx.x * NODES * FIN;
    for (int m = tid; m < NODES * FIN; m += 256) {
        long long gi = xbase + m;
        xs[m] = (gi < (long long)NN * FIN) ? x[gi] : 0.f;
    }
    __syncthreads();

    int tj = tid & 15;          // channel group: channels tj*4 .. tj*4+3
    int tn = tid >> 4;          // node slot: nodes g*16+tn
    int j4 = tj * 4;

    float4 acc[4];
#pragma unroll
    for (int g = 0; g < 4; g++) acc[g] = make_float4(0.f, 0.f, 0.f, 0.f);

#pragma unroll 1
    for (int k4 = 0; k4 < FIN; k4 += 4) {
        float xv[4][4];
#pragma unroll
        for (int g = 0; g < 4; g++) {
            float4 t = *(const float4*)&xs[(g * 16 + tn) * FIN + k4];
            xv[g][0] = t.x; xv[g][1] = t.y; xv[g][2] = t.z; xv[g][3] = t.w;
        }
#pragma unroll
        for (int kk = 0; kk < 4; kk++) {
            float4 wv = *(const float4*)&Ws[(k4 + kk) * 64 + j4];
#pragma unroll
            for (int g = 0; g < 4; g++) {
                float xk = xv[g][kk];
                acc[g].x += xk * wv.x;
                acc[g].y += xk * wv.y;
                acc[g].z += xk * wv.z;
                acc[g].w += xk * wv.w;
            }
        }
    }

    float4 asv = __ldg((const float4*)(a_s + j4));
    float4 adv = __ldg((const float4*)(a_d + j4));
    int nblock = blockIdx.x * NODES;
#pragma unroll
    for (int g = 0; g < 4; g++) {
        int n = nblock + g * 16 + tn;
        float ps = acc[g].x * asv.x + acc[g].y * asv.y + acc[g].z * asv.z + acc[g].w * asv.w;
        float pd = acc[g].x * adv.x + acc[g].y * adv.y + acc[g].z * adv.z + acc[g].w * adv.w;
        ps += __shfl_xor_sync(0xffffffffu, ps, 1);
        ps += __shfl_xor_sync(0xffffffffu, ps, 2);
        pd += __shfl_xor_sync(0xffffffffu, pd, 1);
        pd += __shfl_xor_sync(0xffffffffu, pd, 2);
        if ((tj & 3) == 0 && n < NN) {
            int head = tj >> 2;
            aso[n * 4 + head] = ps * LOG2E;   // pre-scale: exp(e) == exp2(e*log2e)
            ado[n * 4 + head] = pd * LOG2E;
        }
        if (n < NN) {
            __half2 lo = __floats2half2_rn(acc[g].x, acc[g].y);
            __half2 hi = __floats2half2_rn(acc[g].z, acc[g].w);
            uint2 pk;
            pk.x = *reinterpret_cast<unsigned int*>(&lo);
            pk.y = *reinterpret_cast<unsigned int*>(&hi);
            *(uint2*)(hout + n * 64 + j4) = pk;
        }
    }
}

// ---------------- warp-per-destination softmax aggregation (fp16 payload) ----------------
// Logits arrive pre-scaled by log2e; leaky_relu commutes with the positive scale,
// so exp(leaky(e)) == ex2(leaky(e*log2e)) exactly.
// MODE 0: concat (64) + bias + ELU ; 1: head-mean + bias + ELU ; 2: head-mean + bias.
template <int MODE>
__global__ void k_agg(const __half* __restrict__ h, const float* __restrict__ as_,
                      const float* __restrict__ ad_, const float* __restrict__ bias,
                      float* __restrict__ out) {
    int w = (blockIdx.x * blockDim.x + threadIdx.x) >> 5;
    if (w >= NN) return;
    int lane = threadIdx.x & 31;
    int half_ = lane >> 4;         // which edge of the pair
    int q = lane & 15;             // channel group: channels q*4..q*4+3
    int head = q >> 2;
    float adh = __ldg(&ad_[w * 4 + head]);
    float den = 0.f;
    float4 acc = make_float4(0.f, 0.f, 0.f, 0.f);
    int s0 = __ldg(&g_off[w]), s1 = __ldg(&g_off[w + 1]);
    int last = s1 - 1;             // degree >= 1 (self loop)
    for (int i = s0; i < s1; i += 4) {
        int ia = i + half_;
        int ib = i + 2 + half_;
        bool va = ia < s1, vb = ib < s1;
        int sa = __ldg(&g_csr[min(ia, last)]);
        int sb = __ldg(&g_csr[min(ib, last)]);
        float ea = __ldg(&as_[sa * 4 + head]);
        float eb = __ldg(&as_[sb * 4 + head]);
        float4 ha = ldh4(h + sa * 64 + q * 4);
        float4 hb = ldh4(h + sb * 64 + q * 4);
        ea += adh; ea = ea > 0.f ? ea : 0.2f * ea;
        eb += adh; eb = eb > 0.f ? eb : 0.2f * eb;
        float wa = va ? ex2f(ea) : 0.f;
        float wb = vb ? ex2f(eb) : 0.f;
        den += wa + wb;
        acc.x += wa * ha.x + wb * hb.x;
        acc.y += wa * ha.y + wb * hb.y;
        acc.z += wa * ha.z + wb * hb.z;
        acc.w += wa * ha.w + wb * hb.w;
    }
    den   += __shfl_xor_sync(0xffffffffu, den,   16);
    acc.x += __shfl_xor_sync(0xffffffffu, acc.x, 16);
    acc.y += __shfl_xor_sync(0xffffffffu, acc.y, 16);
    acc.z += __shfl_xor_sync(0xffffffffu, acc.z, 16);
    acc.w += __shfl_xor_sync(0xffffffffu, acc.w, 16);
    float inv = 1.f / den;
    float4 o4;
    o4.x = acc.x * inv; o4.y = acc.y * inv; o4.z = acc.z * inv; o4.w = acc.w * inv;
    if (MODE == 0) {
        if (half_ == 0) {
            float4 b4 = __ldg((const float4*)(bias + q * 4));
            o4.x += b4.x; o4.y += b4.y; o4.z += b4.z; o4.w += b4.w;
            o4.x = o4.x > 0.f ? o4.x : expm1f(o4.x);
            o4.y = o4.y > 0.f ? o4.y : expm1f(o4.y);
            o4.z = o4.z > 0.f ? o4.z : expm1f(o4.z);
            o4.w = o4.w > 0.f ? o4.w : expm1f(o4.w);
            *(float4*)(out + w * 64 + q * 4) = o4;
        }
    } else {
#pragma unroll
        for (int o = 4; o <= 8; o <<= 1) {
            o4.x += __shfl_xor_sync(0xffffffffu, o4.x, o);
            o4.y += __shfl_xor_sync(0xffffffffu, o4.y, o);
            o4.z += __shfl_xor_sync(0xffffffffu, o4.z, o);
            o4.w += __shfl_xor_sync(0xffffffffu, o4.w, o);
        }
        if (half_ == 0 && q < 4) {
            float4 b4 = __ldg((const float4*)(bias + q * 4));
            float4 v;
            v.x = 0.25f * o4.x + b4.x;
            v.y = 0.25f * o4.y + b4.y;
            v.z = 0.25f * o4.z + b4.z;
            v.w = 0.25f * o4.w + b4.w;
            if (MODE == 1) {
                v.x = v.x > 0.f ? v.x : expm1f(v.x);
                v.y = v.y > 0.f ? v.y : expm1f(v.y);
                v.z = v.z > 0.f ? v.z : expm1f(v.z);
                v.w = v.w > 0.f ? v.w : expm1f(v.w);
            }
            *(float4*)(out + w * 16 + q * 4) = v;
        }
    }
}

// --------- mean pooling (sorted batch -> run-length) + re-zero g_deg slice ---------
__global__ void k_pool(const void* bp) {
    constexpr int NPB = 1024;           // nodes per block
    for (int j = threadIdx.x; j < NPB; j += blockDim.x) {
        int n = blockIdx.x * NPB + j;
        if (n < NN) g_deg[n] = 0;
    }
    int c = threadIdx.x & 15;
    int nrel = threadIdx.x >> 4;        // 0..15
    int base = blockIdx.x * NPB;
    float acc = 0.f, cnt = 0.f;
    int bcur = -1;
    for (int k = 0; k < NPB / 16; k++) {
        int n = base + k * 16 + nrel;
        if (n >= NN) break;
        int b = g_is64 ? (int)((const long long*)bp)[n] : ((const int*)bp)[n];
        if (b != bcur) {
            if (bcur >= 0) {
                atomicAdd(&g_pool[bcur * 16 + c], acc);
                if (c == 0) atomicAdd(&g_cnt[bcur], cnt);
            }
            bcur = b; acc = 0.f; cnt = 0.f;
        }
        acc += g_x3[n * 16 + c];
        cnt += 1.f;
    }
    if (bcur >= 0) {
        atomicAdd(&g_pool[bcur * 16 + c], acc);
        if (c == 0) atomicAdd(&g_cnt[bcur], cnt);
    }
}

// ---------------- tiny MLP head (single block) — also resets pool state ----------------
__global__ void k_mlp(const float* __restrict__ stats,
                      const float* __restrict__ fw1, const float* __restrict__ fb1,
                      const float* __restrict__ fw2, const float* __restrict__ fb2,
                      const float* __restrict__ fw3, const float* __restrict__ fb3,
                      float* __restrict__ out) {
    __shared__ float zin[BB * 32];
    __shared__ float z1[BB * 32];
    __shared__ float z2[BB * 16];
    int tid = threadIdx.x;
    for (int t = tid; t < BB * 32; t += blockDim.x) {
        int b = t >> 5, k = t & 31;
        zin[t] = (k < 16) ? g_pool[b * 16 + k] / fmaxf(g_cnt[b], 1.f)
                          : stats[b * 16 + (k - 16)];
    }
    __syncthreads();
    if (tid < BB * 16) g_pool[tid] = 0.f;
    if (tid < BB) g_cnt[tid] = 0.f;
    for (int t = tid; t < BB * 32; t += blockDim.x) {
        int b = t >> 5, j = t & 31;
        float a = fb1[j];
#pragma unroll
        for (int k = 0; k < 32; k++) a += zin[b * 32 + k] * fw1[k * 32 + j];
        z1[t] = fmaxf(a, 0.f);
    }
    __syncthreads();
    for (int t = tid; t < BB * 16; t += blockDim.x) {
        int b = t >> 4, j = t & 15;
        float a = fb2[j];
#pragma unroll
        for (int k = 0; k < 32; k++) a += z1[b * 32 + k] * fw2[k * 16 + j];
        z2[t] = fmaxf(a, 0.f);
    }
    __syncthreads();
    for (int t = tid; t < BB; t += blockDim.x) {
        float a = fb3[0];
#pragma unroll
        for (int k = 0; k < 16; k++) a += z2[t * 16 + k] * fw3[k];
        out[t] = a;
    }
}

// ---------------- launcher ----------------
extern "C" void kernel_launch(void* const* d_in, const int* in_sizes, int n_in,
                              void* d_out, int out_size) {
    const float* x     = (const float*)d_in[0];
    const float* stats = (const float*)d_in[1];
    const float* W1  = (const float*)d_in[2];
    const float* a1s = (const float*)d_in[3];
    const float* a1d = (const float*)d_in[4];
    const float* b1  = (const float*)d_in[5];
    const float* W2  = (const float*)d_in[6];
    const float* a2s = (const float*)d_in[7];
    const float* a2d = (const float*)d_in[8];
    const float* b2  = (const float*)d_in[9];
    const float* W3  = (const float*)d_in[10];
    const float* a3s = (const float*)d_in[11];
    const float* a3d = (const float*)d_in[12];
    const float* b3  = (const float*)d_in[13];
    const float* fw1 = (const float*)d_in[14];
    const float* fb1 = (const float*)d_in[15];
    const float* fw2 = (const float*)d_in[16];
    const float* fb2 = (const float*)d_in[17];
    const float* fw3 = (const float*)d_in[18];
    const float* fb3 = (const float*)d_in[19];
    const void*  edges = d_in[20];
    const void*  batch = d_in[21];
    float* out = (float*)d_out;

    __half* dg_h; cudaGetSymbolAddress((void**)&dg_h,  g_h16);
    float* dg_as; cudaGetSymbolAddress((void**)&dg_as, g_as);
    float* dg_ad; cudaGetSymbolAddress((void**)&dg_ad, g_ad);
    float* dg_x1; cudaGetSymbolAddress((void**)&dg_x1, g_x1);
    float* dg_x2; cudaGetSymbolAddress((void**)&dg_x2, g_x2);
    float* dg_x3; cudaGetSymbolAddress((void**)&dg_x3, g_x3);

    // one-time stream/event creation (no device memory allocation involved)
    static cudaStream_t s_aux = nullptr;
    static cudaEvent_t ev_fork = nullptr, ev_join = nullptr;
    if (!s_aux) {
        cudaStreamCreateWithFlags(&s_aux, cudaStreamNonBlocking);
        cudaEventCreateWithFlags(&ev_fork, cudaEventDisableTiming);
        cudaEventCreateWithFlags(&ev_join, cudaEventDisableTiming);
    }

    const int NB_SCAN = (NN + 1023) / 1024;   // 98
    const int TGRID = (NN + 63) / 64;          // 1563 blocks of 256 (64 nodes each)
    const int AGRID = (NN * 32 + 255) / 256;   // warp per node

    // fork aux stream off the capture stream (t16-layer1 is graph-independent)
    cudaEventRecord(ev_fork, 0);
    cudaStreamWaitEvent(s_aux, ev_fork, 0);

    k_init<<<1, 32>>>((const int*)edges);                               // launch 0
    k_build<<<(ETOT + 255) / 256, 256>>>(edges);                        // 1
    k_scan<<<NB_SCAN, 1024>>>();                                        // 2
    k_scatter<<<(ETOT + 255) / 256, 256>>>();                           // 3 (profiled)
    // layer-1 transform runs CONCURRENTLY with the build chain
    k_transform<16><<<TGRID, 256, 0, s_aux>>>(x, W1, a1s, a1d, dg_h, dg_as, dg_ad); // 4
    cudaEventRecord(ev_join, s_aux);
    cudaStreamWaitEvent(0, ev_join, 0);

    // layer 1 aggregation: concat + ELU
    k_agg<0><<<AGRID, 256>>>(dg_h, dg_as, dg_ad, b1, dg_x1);            // 5
    // layer 2: 64 -> head-mean 16 + ELU
    k_transform<64><<<TGRID, 256>>>(dg_x1, W2, a2s, a2d, dg_h, dg_as, dg_ad); // 6
    k_agg<1><<<AGRID, 256>>>(dg_h, dg_as, dg_ad, b2, dg_x2);            // 7
    // layer 3: 16 -> head-mean 16 (no ELU)
    k_transform<16><<<TGRID, 256>>>(dg_x2, W3, a3s, a3d, dg_h, dg_as, dg_ad); // 8
    k_agg<2><<<AGRID, 256>>>(dg_h, dg_as, dg_ad, b3, dg_x3);            // 9

    // pooling (+ deg reset) + MLP (+ pool reset)
    k_pool<<<NB_SCAN, 256>>>(batch);                                    // 10
    k_mlp<<<1, 1024>>>(stats, fw1, fb1, fw2, fb2, fw3, fb3, out);       // 11
}

// round 16
// speedup vs baseline: 1.6643x; 1.0802x over previous
#include <cuda_runtime.h>
#include <cuda_fp16.h>
#include <cstdint>

#define NN 100000
#define EE 1600000
#define ETOT (EE + NN)
#define CSRMAX (ETOT + 3 * NN)    // padded CSR upper bound
#define BB 64

// ---------------- device scratch (static: no allocs allowed) ----------------
__device__ int    g_is64;
__device__ int    g_esrc[ETOT];
__device__ int    g_edst[ETOT];
__device__ int    g_deg[NN];          // zero-initialized; k_pool re-zeroes each replay
__device__ int    g_off[NN + 1];      // PADDED offsets (each segment multiple of 4)
__device__ int    g_cursor[NN];
__device__ int    g_csr[CSRMAX];
__device__ __half g_h16[(NN + 1) * 64]; // +1 dummy row (stays zero; weight is 0)
__device__ float  g_as[(NN + 1) * 4];   // logits pre-scaled by log2(e); dummy = -1e30
__device__ float  g_ad[(NN + 1) * 4];
__device__ float  g_x1[NN * 64];
__device__ float  g_x2[NN * 16];
__device__ float  g_x3[NN * 16];
__device__ float  g_pool[BB * 16];    // zero-initialized; k_mlp re-zeroes after read
__device__ float  g_cnt[BB];

#define LOG2E 1.4426950408889634f

__device__ __forceinline__ float ex2f(float x) {
    float r; asm("ex2.approx.f32 %0, %1;" : "=f"(r) : "f"(x)); return r;
}

// load 4 contiguous halves as float4 with a single LDG.64
__device__ __forceinline__ float4 ldh4(const __half* p) {
    uint2 r = *(const uint2*)p;
    __half2 h0 = *reinterpret_cast<__half2*>(&r.x);
    __half2 h1 = *reinterpret_cast<__half2*>(&r.y);
    float2 f0 = __half22float2(h0), f1 = __half22float2(h1);
    return make_float4(f0.x, f0.y, f1.x, f1.y);
}

// ------------- init: dtype detection only (1 warp) -------------
__global__ void k_init(const int* e) {
    if (threadIdx.x == 0) {
        int z = 0;
        for (int j = 0; j < 64; j++) z |= e[2 * j + 1];   // high words if int64
        g_is64 = (z == 0) ? 1 : 0;
    }
}

// build edge arrays (+ self loops) and histogram dst
__global__ void k_build(const void* ep) {
    int i = blockIdx.x * blockDim.x + threadIdx.x;
    if (i >= ETOT) return;
    int s, d;
    if (i < EE) {
        if (g_is64) {
            const long long* e = (const long long*)ep;
            s = (int)e[i]; d = (int)e[EE + i];
        } else {
            const int* e = (const int*)ep;
            s = e[i]; d = e[EE + i];
        }
    } else {
        s = d = i - EE;    // self loop
    }
    g_esrc[i] = s;
    g_edst[i] = d;
    atomicAdd(&g_deg[d], 1);
}

// ------------- exclusive scan over PADDED degrees + pad-slot fill -------------
// Block b: (1) reduce-sum padded degrees below b*1024, (2) block-scan own 1024
// padded degrees, (3) write padded offsets + cursors, (4) fill the <=3 padding
// slots per node with the dummy node NN, (5) plant dummy logits.
__global__ void k_scan() {
    __shared__ int warp_sums[32];
    __shared__ int carry_s;
    int bid = blockIdx.x, tid = threadIdx.x;
    int lane = tid & 31, wid = tid >> 5;
    int pre = bid * 1024;

    // ---- carry = sum of padded degrees below this block ----
    int c = 0;
    for (int j = tid; j < pre; j += 1024) c += (g_deg[j] + 3) & ~3;
#pragma unroll
    for (int o = 16; o >= 1; o >>= 1) c += __shfl_xor_sync(0xffffffffu, c, o);
    if (lane == 0) warp_sums[wid] = c;
    __syncthreads();
    if (wid == 0) {
        int s = warp_sums[lane];
#pragma unroll
        for (int o = 16; o >= 1; o >>= 1) s += __shfl_xor_sync(0xffffffffu, s, o);
        if (lane == 0) carry_s = s;
    }
    __syncthreads();
    int carry = carry_s;
    __syncthreads();

    // ---- exclusive scan of own 1024 padded degrees ----
    int i = pre + tid;
    int deg = (i < NN) ? g_deg[i] : 0;
    int v = (deg + 3) & ~3;
    int x = v;
#pragma unroll
    for (int o = 1; o < 32; o <<= 1) {
        int y = __shfl_up_sync(0xffffffffu, x, o);
        if (lane >= o) x += y;
    }
    if (lane == 31) warp_sums[wid] = x;
    __syncthreads();
    if (wid == 0) {
        int s = warp_sums[lane];
#pragma unroll
        for (int o = 1; o < 32; o <<= 1) {
            int y = __shfl_up_sync(0xffffffffu, s, o);
            if (lane >= o) s += y;
        }
        warp_sums[lane] = s;
    }
    __syncthreads();
    int excl = x - v + (wid > 0 ? warp_sums[wid - 1] : 0) + carry;
    if (i < NN) {
        g_off[i] = excl;
        g_cursor[i] = excl;
        // fill padding slots with the dummy node (weight 0 in agg)
        for (int p = excl + deg; p < excl + v; p++) g_csr[p] = NN;
        if (i == NN - 1) g_off[NN] = excl + v;
    }
    // plant dummy-node logits (ex2 of -2e29 -> 0)
    if (bid == 0 && tid < 4) {
        g_as[NN * 4 + tid] = -1e30f;
        g_ad[NN * 4 + tid] = -1e30f;
    }
}

__global__ void k_scatter() {
    int i = blockIdx.x * blockDim.x + threadIdx.x;
    if (i >= ETOT) return;
    int d = g_edst[i];
    int p = atomicAdd(&g_cursor[d], 1);
    g_csr[p] = g_esrc[i];
}

// ---------------- transform: k4-vectorized, 4 channels x 4 nodes per thread ----------------
// __launch_bounds__(256,6): 40 regs, ~64% occ (verified R14: 26.3 -> 16.6us).
// Logits written pre-scaled by log2(e) so agg can use raw ex2.approx.
template <int FIN>
__global__ void __launch_bounds__(256, 6)
k_transform(const float* __restrict__ x, const float* __restrict__ W,
            const float* __restrict__ a_s, const float* __restrict__ a_d,
            __half* __restrict__ hout, float* __restrict__ aso,
            float* __restrict__ ado) {
    constexpr int NODES = 64;
    __shared__ float Ws[FIN * 64];          // [k][64]
    __shared__ float xs[NODES * FIN];       // [node][FIN]
    int tid = threadIdx.x;
    for (int k = tid; k < FIN * 64; k += 256) Ws[k] = W[k];
    long long xbase = (long long)blockIdx.x * NODES * FIN;
    for (int m = tid; m < NODES * FIN; m += 256) {
        long long gi = xbase + m;
        xs[m] = (gi < (long long)NN * FIN) ? x[gi] : 0.f;
    }
    __syncthreads();

    int tj = tid & 15;          // channel group: channels tj*4 .. tj*4+3
    int tn = tid >> 4;          // node slot: nodes g*16+tn
    int j4 = tj * 4;

    float4 acc[4];
#pragma unroll
    for (int g = 0; g < 4; g++) acc[g] = make_float4(0.f, 0.f, 0.f, 0.f);

#pragma unroll 1
    for (int k4 = 0; k4 < FIN; k4 += 4) {
        float xv[4][4];
#pragma unroll
        for (int g = 0; g < 4; g++) {
            float4 t = *(const float4*)&xs[(g * 16 + tn) * FIN + k4];
            xv[g][0] = t.x; xv[g][1] = t.y; xv[g][2] = t.z; xv[g][3] = t.w;
        }
#pragma unroll
        for (int kk = 0; kk < 4; kk++) {
            float4 wv = *(const float4*)&Ws[(k4 + kk) * 64 + j4];
#pragma unroll
            for (int g = 0; g < 4; g++) {
                float xk = xv[g][kk];
                acc[g].x += xk * wv.x;
                acc[g].y += xk * wv.y;
                acc[g].z += xk * wv.z;
                acc[g].w += xk * wv.w;
            }
        }
    }

    float4 asv = __ldg((const float4*)(a_s + j4));
    float4 adv = __ldg((const float4*)(a_d + j4));
    int nblock = blockIdx.x * NODES;
#pragma unroll
    for (int g = 0; g < 4; g++) {
        int n = nblock + g * 16 + tn;
        float ps = acc[g].x * asv.x + acc[g].y * asv.y + acc[g].z * asv.z + acc[g].w * asv.w;
        float pd = acc[g].x * adv.x + acc[g].y * adv.y + acc[g].z * adv.z + acc[g].w * adv.w;
        ps += __shfl_xor_sync(0xffffffffu, ps, 1);
        ps += __shfl_xor_sync(0xffffffffu, ps, 2);
        pd += __shfl_xor_sync(0xffffffffu, pd, 1);
        pd += __shfl_xor_sync(0xffffffffu, pd, 2);
        if ((tj & 3) == 0 && n < NN) {
            int head = tj >> 2;
            aso[n * 4 + head] = ps * LOG2E;   // pre-scale: exp(e) == exp2(e*log2e)
            ado[n * 4 + head] = pd * LOG2E;
        }
        if (n < NN) {
            __half2 lo = __floats2half2_rn(acc[g].x, acc[g].y);
            __half2 hi = __floats2half2_rn(acc[g].z, acc[g].w);
            uint2 pk;
            pk.x = *reinterpret_cast<unsigned int*>(&lo);
            pk.y = *reinterpret_cast<unsigned int*>(&hi);
            *(uint2*)(hout + n * 64 + j4) = pk;
        }
    }
}

// ---------------- warp-per-destination softmax aggregation (fp16 payload) ----------------
// CSR segments are padded to multiples of 4 with dummy node NN (logit -1e30 ->
// weight exactly 0), so the loop is branch-free: no tail, no clamps, no selects.
// leaky_relu == fmaxf(e, 0.2e) exactly. Logits pre-scaled by log2e -> bare ex2.
// MODE 0: concat (64) + bias + ELU ; 1: head-mean + bias + ELU ; 2: head-mean + bias.
template <int MODE>
__global__ void k_agg(const __half* __restrict__ h, const float* __restrict__ as_,
                      const float* __restrict__ ad_, const float* __restrict__ bias,
                      float* __restrict__ out) {
    int w = (blockIdx.x * blockDim.x + threadIdx.x) >> 5;
    if (w >= NN) return;
    int lane = threadIdx.x & 31;
    int half_ = lane >> 4;         // which edge of the pair
    int q = lane & 15;             // channel group: channels q*4..q*4+3
    int head = q >> 2;
    float adh = __ldg(&ad_[w * 4 + head]);
    float den = 0.f;
    float4 acc = make_float4(0.f, 0.f, 0.f, 0.f);
    int s0 = __ldg(&g_off[w]), s1 = __ldg(&g_off[w + 1]);
    for (int i = s0 + half_; i < s1; i += 4) {
        int sa = __ldg(&g_csr[i]);
        int sb = __ldg(&g_csr[i + 2]);
        float ea = __ldg(&as_[sa * 4 + head]);
        float eb = __ldg(&as_[sb * 4 + head]);
        float4 ha = ldh4(h + sa * 64 + q * 4);
        float4 hb = ldh4(h + sb * 64 + q * 4);
        ea += adh; ea = fmaxf(ea, 0.2f * ea);   // leaky_relu, exact
        eb += adh; eb = fmaxf(eb, 0.2f * eb);
        float wa = ex2f(ea);
        float wb = ex2f(eb);
        den += wa + wb;
        acc.x += wa * ha.x + wb * hb.x;
        acc.y += wa * ha.y + wb * hb.y;
        acc.z += wa * ha.z + wb * hb.z;
        acc.w += wa * ha.w + wb * hb.w;
    }
    den   += __shfl_xor_sync(0xffffffffu, den,   16);
    acc.x += __shfl_xor_sync(0xffffffffu, acc.x, 16);
    acc.y += __shfl_xor_sync(0xffffffffu, acc.y, 16);
    acc.z += __shfl_xor_sync(0xffffffffu, acc.z, 16);
    acc.w += __shfl_xor_sync(0xffffffffu, acc.w, 16);
    float inv = 1.f / den;
    float4 o4;
    o4.x = acc.x * inv; o4.y = acc.y * inv; o4.z = acc.z * inv; o4.w = acc.w * inv;
    if (MODE == 0) {
        if (half_ == 0) {
            float4 b4 = __ldg((const float4*)(bias + q * 4));
            o4.x += b4.x; o4.y += b4.y; o4.z += b4.z; o4.w += b4.w;
            o4.x = o4.x > 0.f ? o4.x : expm1f(o4.x);
            o4.y = o4.y > 0.f ? o4.y : expm1f(o4.y);
            o4.z = o4.z > 0.f ? o4.z : expm1f(o4.z);
            o4.w = o4.w > 0.f ? o4.w : expm1f(o4.w);
            *(float4*)(out + w * 64 + q * 4) = o4;
        }
    } else {
#pragma unroll
        for (int o = 4; o <= 8; o <<= 1) {
            o4.x += __shfl_xor_sync(0xffffffffu, o4.x, o);
            o4.y += __shfl_xor_sync(0xffffffffu, o4.y, o);
            o4.z += __shfl_xor_sync(0xffffffffu, o4.z, o);
            o4.w += __shfl_xor_sync(0xffffffffu, o4.w, o);
        }
        if (half_ == 0 && q < 4) {
            float4 b4 = __ldg((const float4*)(bias + q * 4));
            float4 v;
            v.x = 0.25f * o4.x + b4.x;
            v.y = 0.25f * o4.y + b4.y;
            v.z = 0.25f * o4.z + b4.z;
            v.w = 0.25f * o4.w + b4.w;
            if (MODE == 1) {
                v.x = v.x > 0.f ? v.x : expm1f(v.x);
                v.y = v.y > 0.f ? v.y : expm1f(v.y);
                v.z = v.z > 0.f ? v.z : expm1f(v.z);
                v.w = v.w > 0.f ? v.w : expm1f(v.w);
            }
            *(float4*)(out + w * 16 + q * 4) = v;
        }
    }
}

// --------- mean pooling (sorted batch -> run-length) + re-zero g_deg slice ---------
__global__ void k_pool(const void* bp) {
    constexpr int NPB = 1024;           // nodes per block
    for (int j = threadIdx.x; j < NPB; j += blockDim.x) {
        int n = blockIdx.x * NPB + j;
        if (n < NN) g_deg[n] = 0;
    }
    int c = threadIdx.x & 15;
    int nrel = threadIdx.x >> 4;        // 0..15
    int base = blockIdx.x * NPB;
    float acc = 0.f, cnt = 0.f;
    int bcur = -1;
    for (int k = 0; k < NPB / 16; k++) {
        int n = base + k * 16 + nrel;
        if (n >= NN) break;
        int b = g_is64 ? (int)((const long long*)bp)[n] : ((const int*)bp)[n];
        if (b != bcur) {
            if (bcur >= 0) {
                atomicAdd(&g_pool[bcur * 16 + c], acc);
                if (c == 0) atomicAdd(&g_cnt[bcur], cnt);
            }
            bcur = b; acc = 0.f; cnt = 0.f;
        }
        acc += g_x3[n * 16 + c];
        cnt += 1.f;
    }
    if (bcur >= 0) {
        atomicAdd(&g_pool[bcur * 16 + c], acc);
        if (c == 0) atomicAdd(&g_cnt[bcur], cnt);
    }
}

// ---------------- tiny MLP head (single block) — also resets pool state ----------------
__global__ void k_mlp(const float* __restrict__ stats,
                      const float* __restrict__ fw1, const float* __restrict__ fb1,
                      const float* __restrict__ fw2, const float* __restrict__ fb2,
                      const float* __restrict__ fw3, const float* __restrict__ fb3,
                      float* __restrict__ out) {
    __shared__ float zin[BB * 32];
    __shared__ float z1[BB * 32];
    __shared__ float z2[BB * 16];
    int tid = threadIdx.x;
    for (int t = tid; t < BB * 32; t += blockDim.x) {
        int b = t >> 5, k = t & 31;
        zin[t] = (k < 16) ? g_pool[b * 16 + k] / fmaxf(g_cnt[b], 1.f)
                          : stats[b * 16 + (k - 16)];
    }
    __syncthreads();
    if (tid < BB * 16) g_pool[tid] = 0.f;
    if (tid < BB) g_cnt[tid] = 0.f;
    for (int t = tid; t < BB * 32; t += blockDim.x) {
        int b = t >> 5, j = t & 31;
        float a = fb1[j];
#pragma unroll
        for (int k = 0; k < 32; k++) a += zin[b * 32 + k] * fw1[k * 32 + j];
        z1[t] = fmaxf(a, 0.f);
    }
    __syncthreads();
    for (int t = tid; t < BB * 16; t += blockDim.x) {
        int b = t >> 4, j = t & 15;
        float a = fb2[j];
#pragma unroll
        for (int k = 0; k < 32; k++) a += z1[b * 32 + k] * fw2[k * 16 + j];
        z2[t] = fmaxf(a, 0.f);
    }
    __syncthreads();
    for (int t = tid; t < BB; t += blockDim.x) {
        float a = fb3[0];
#pragma unroll
        for (int k = 0; k < 16; k++) a += z2[t * 16 + k] * fw3[k];
        out[t] = a;
    }
}

// ---------------- launcher ----------------
extern "C" void kernel_launch(void* const* d_in, const int* in_sizes, int n_in,
                              void* d_out, int out_size) {
    const float* x     = (const float*)d_in[0];
    const float* stats = (const float*)d_in[1];
    const float* W1  = (const float*)d_in[2];
    const float* a1s = (const float*)d_in[3];
    const float* a1d = (const float*)d_in[4];
    const float* b1  = (const float*)d_in[5];
    const float* W2  = (const float*)d_in[6];
    const float* a2s = (const float*)d_in[7];
    const float* a2d = (const float*)d_in[8];
    const float* b2  = (const float*)d_in[9];
    const float* W3  = (const float*)d_in[10];
    const float* a3s = (const float*)d_in[11];
    const float* a3d = (const float*)d_in[12];
    const float* b3  = (const float*)d_in[13];
    const float* fw1 = (const float*)d_in[14];
    const float* fb1 = (const float*)d_in[15];
    const float* fw2 = (const float*)d_in[16];
    const float* fb2 = (const float*)d_in[17];
    const float* fw3 = (const float*)d_in[18];
    const float* fb3 = (const float*)d_in[19];
    const void*  edges = d_in[20];
    const void*  batch = d_in[21];
    float* out = (float*)d_out;

    __half* dg_h; cudaGetSymbolAddress((void**)&dg_h,  g_h16);
    float* dg_as; cudaGetSymbolAddress((void**)&dg_as, g_as);
    float* dg_ad; cudaGetSymbolAddress((void**)&dg_ad, g_ad);
    float* dg_x1; cudaGetSymbolAddress((void**)&dg_x1, g_x1);
    float* dg_x2; cudaGetSymbolAddress((void**)&dg_x2, g_x2);
    float* dg_x3; cudaGetSymbolAddress((void**)&dg_x3, g_x3);

    // one-time stream/event creation (no device memory allocation involved)
    static cudaStream_t s_aux = nullptr;
    static cudaEvent_t ev_fork = nullptr, ev_join = nullptr;
    if (!s_aux) {
        cudaStreamCreateWithFlags(&s_aux, cudaStreamNonBlocking);
        cudaEventCreateWithFlags(&ev_fork, cudaEventDisableTiming);
        cudaEventCreateWithFlags(&ev_join, cudaEventDisableTiming);
    }

    const int NB_SCAN = (NN + 1023) / 1024;   // 98
    const int TGRID = (NN + 63) / 64;          // 1563 blocks of 256 (64 nodes each)
    const int AGRID = (NN * 32 + 255) / 256;   // warp per node

    // fork aux stream off the capture stream (t16-layer1 is graph-independent)
    cudaEventRecord(ev_fork, 0);
    cudaStreamWaitEvent(s_aux, ev_fork, 0);

    k_init<<<1, 32>>>((const int*)edges);                               // launch 0
    k_build<<<(ETOT + 255) / 256, 256>>>(edges);                        // 1
    k_scan<<<NB_SCAN, 1024>>>();                                        // 2
    k_scatter<<<(ETOT + 255) / 256, 256>>>();                           // 3 (profiled)
    // layer-1 transform runs CONCURRENTLY with the build chain
    k_transform<16><<<TGRID, 256, 0, s_aux>>>(x, W1, a1s, a1d, dg_h, dg_as, dg_ad); // 4
    cudaEventRecord(ev_join, s_aux);
    cudaStreamWaitEvent(0, ev_join, 0);

    // layer 1 aggregation: concat + ELU
    k_agg<0><<<AGRID, 256>>>(dg_h, dg_as, dg_ad, b1, dg_x1);            // 5
    // layer 2: 64 -> head-mean 16 + ELU
    k_transform<64><<<TGRID, 256>>>(dg_x1, W2, a2s, a2d, dg_h, dg_as, dg_ad); // 6
    k_agg<1><<<AGRID, 256>>>(dg_h, dg_as, dg_ad, b2, dg_x2);            // 7
    // layer 3: 16 -> head-mean 16 (no ELU)
    k_transform<16><<<TGRID, 256>>>(dg_x2, W3, a3s, a3d, dg_h, dg_as, dg_ad); // 8
    k_agg<2><<<AGRID, 256>>>(dg_h, dg_as, dg_ad, b3, dg_x3);            // 9

    // pooling (+ deg reset) + MLP (+ pool reset)
    k_pool<<<NB_SCAN, 256>>>(batch);                                    // 10
    k_mlp<<<1, 1024>>>(stats, fw1, fb1, fw2, fb2, fw3, fb3, out);       // 11
}